// round 3
// baseline (speedup 1.0000x reference)
#include <cuda_runtime.h>
#include <cuda_bf16.h>

#define N_NODES 65536
#define N_PER   2048
#define BATCH   32
#define E_EDGES 1048576
#define D       128
#define C_OUT   8

// ---------------- scratch (device globals: allocation-free) ----------------
__device__ float g_bufA[N_NODES * D];
__device__ float g_bufB[N_NODES * D];
__device__ float g_bufC[N_NODES * D];
__device__ float g_deg[N_NODES];
__device__ float g_dinv[N_NODES];
__device__ float g_gbias[BATCH * D];
__device__ float g_sum[D];
__device__ float g_sumsq[D];
__device__ float g_scale[D];
__device__ float g_shift[D];

// buffer selectors (compile-time) — avoids any host-side symbol lookup
__device__ __forceinline__ float* buf_ptr_dev(int sel) {
    switch (sel) {
        case 1: return g_bufA;
        case 2: return g_bufB;
        default: return g_bufC;
    }
}

// ---------------- helpers ----------------
__device__ __forceinline__ void atomic_add_f4(float4* addr, float4 v) {
    asm volatile("red.global.add.v4.f32 [%0], {%1,%2,%3,%4};"
                 :: "l"(addr), "f"(v.x), "f"(v.y), "f"(v.z), "f"(v.w) : "memory");
}

// ---------------- degree / norm ----------------
__global__ void deg_init_kernel() {
    int i = blockIdx.x * 256 + threadIdx.x;
    if (i < N_NODES) g_deg[i] = 1.0f;      // self-loop
    if (i < D) { g_sum[i] = 0.0f; g_sumsq[i] = 0.0f; }
}

__global__ void deg_count_kernel(const int* __restrict__ dst) {
    int e = blockIdx.x * 256 + threadIdx.x;
    if (e < E_EDGES) atomicAdd(&g_deg[dst[e]], 1.0f);
}

__global__ void dinv_kernel() {
    int i = blockIdx.x * 256 + threadIdx.x;
    if (i < N_NODES) g_dinv[i] = rsqrtf(g_deg[i]);
}

// ---------------- SGEMM: C[M,128] = A[M,128] @ B[128,128] (+epilogue) ------
// EPI: 0=none, 1=+bias[col], 2=relu(+bias[col]), 3=+g_gbias[graph(row)][col]
// BN_A: A-load transform a' = max(0, a*scale[k]+shift[k])
// ASEL/CSEL: 0 = external pointer, 1/2/3 = g_bufA/g_bufB/g_bufC
template<int EPI, bool BN_A, int ASEL, int CSEL>
__global__ __launch_bounds__(256) void sgemm128(const float* __restrict__ Aext,
                                                const float* __restrict__ B,
                                                float* __restrict__ Cext,
                                                const float* __restrict__ bias) {
    const float* A = (ASEL == 0) ? Aext : buf_ptr_dev(ASEL);
    float* Cm      = (CSEL == 0) ? Cext : buf_ptr_dev(CSEL);

    __shared__ float As[16][128];
    __shared__ float Bs[16][128];
    const int tid = threadIdx.x;
    const int tr = tid >> 4;          // 0..15
    const int tc = tid & 15;          // 0..15
    const int rowBase = blockIdx.x * 128;

    float acc[8][8];
#pragma unroll
    for (int i = 0; i < 8; i++)
#pragma unroll
        for (int j = 0; j < 8; j++) acc[i][j] = 0.0f;

    for (int k0 = 0; k0 < 128; k0 += 16) {
#pragma unroll
        for (int s = 0; s < 2; s++) {
            int id = tid * 2 + s;                    // 0..511
            // A tile: 128 rows x 16 cols -> transposed store
            int ar = id >> 2;
            int ak = (id & 3) * 4;
            float4 av = *(const float4*)(A + (rowBase + ar) * D + k0 + ak);
            if (BN_A) {
                av.x = fmaxf(fmaf(av.x, g_scale[k0 + ak + 0], g_shift[k0 + ak + 0]), 0.0f);
                av.y = fmaxf(fmaf(av.y, g_scale[k0 + ak + 1], g_shift[k0 + ak + 1]), 0.0f);
                av.z = fmaxf(fmaf(av.z, g_scale[k0 + ak + 2], g_shift[k0 + ak + 2]), 0.0f);
                av.w = fmaxf(fmaf(av.w, g_scale[k0 + ak + 3], g_shift[k0 + ak + 3]), 0.0f);
            }
            As[ak + 0][ar] = av.x;
            As[ak + 1][ar] = av.y;
            As[ak + 2][ar] = av.z;
            As[ak + 3][ar] = av.w;
            // B tile: 16 rows x 128 cols
            int br = id >> 5;
            int bc = (id & 31) * 4;
            float4 bv = *(const float4*)(B + (k0 + br) * D + bc);
            *(float4*)&Bs[br][bc] = bv;
        }
        __syncthreads();
#pragma unroll
        for (int kk = 0; kk < 16; kk++) {
            float am[8], bn[8];
#pragma unroll
            for (int i = 0; i < 8; i++) am[i] = As[kk][tr * 8 + i];
#pragma unroll
            for (int j = 0; j < 8; j++) bn[j] = Bs[kk][tc * 8 + j];
#pragma unroll
            for (int i = 0; i < 8; i++)
#pragma unroll
                for (int j = 0; j < 8; j++) acc[i][j] = fmaf(am[i], bn[j], acc[i][j]);
        }
        __syncthreads();
    }

#pragma unroll
    for (int i = 0; i < 8; i++) {
        int row = rowBase + tr * 8 + i;
        const float* brow = bias;
        if (EPI == 3) brow = g_gbias + (row >> 11) * D;   // N_PER = 2048
#pragma unroll
        for (int j = 0; j < 8; j++) {
            int col = tc * 8 + j;
            float v = acc[i][j];
            if (EPI >= 1) v += brow[col];
            if (EPI == 2) v = fmaxf(v, 0.0f);
            Cm[row * D + col] = v;
        }
    }
}

// ---------------- GCN scatter ----------------
// acc[i] = dinv[i]^2 * t[i]   (self-loop term)   t=TSEL buffer, acc=OSEL buffer
template<int TSEL, int OSEL>
__global__ void scatter_init_kernel() {
    const float* t = buf_ptr_dev(TSEL);
    float* acc = buf_ptr_dev(OSEL);
    int idx = blockIdx.x * 256 + threadIdx.x;          // over N*D/4
    int node = idx >> 5;                               // 32 float4 per row
    float dv = g_dinv[node];
    float nn = dv * dv;
    float4 v = ((const float4*)t)[idx];
    v.x *= nn; v.y *= nn; v.z *= nn; v.w *= nn;
    ((float4*)acc)[idx] = v;
}

// one warp per edge: acc[dst] += dinv[src]*dinv[dst] * t[src]
template<int TSEL, int OSEL>
__global__ __launch_bounds__(256) void scatter_edges_kernel(const int* __restrict__ src,
                                                            const int* __restrict__ dst) {
    const float* t = buf_ptr_dev(TSEL);
    float* acc = buf_ptr_dev(OSEL);
    int e = blockIdx.x * 8 + (threadIdx.x >> 5);
    int lane = threadIdx.x & 31;
    int s = src[e];
    int d = dst[e];
    float nrm = g_dinv[s] * g_dinv[d];
    float4 v = ((const float4*)(t + s * D))[lane];
    v.x *= nrm; v.y *= nrm; v.z *= nrm; v.w *= nrm;
    atomic_add_f4(((float4*)(acc + d * D)) + lane, v);
}

template<bool RELU, int ISEL, int OSEL>
__global__ void add_bias_kernel(const float* __restrict__ bias) {
    const float* acc = buf_ptr_dev(ISEL);
    float* out = buf_ptr_dev(OSEL);
    int idx = blockIdx.x * 256 + threadIdx.x;          // over N*D/4
    int c4 = idx & 31;
    float4 b = ((const float4*)bias)[c4];
    float4 v = ((const float4*)acc)[idx];
    v.x += b.x; v.y += b.y; v.z += b.z; v.w += b.w;
    if (RELU) {
        v.x = fmaxf(v.x, 0.0f); v.y = fmaxf(v.y, 0.0f);
        v.z = fmaxf(v.z, 0.0f); v.w = fmaxf(v.w, 0.0f);
    }
    ((float4*)out)[idx] = v;
}

// ---------------- per-graph bias from src/dest gathered vectors ------------
// g_gbias[b][c] = ff_b[c] + sum_k h2[srow][k]*W[128+k][c] + h2[drow][k]*W[256+k][c]
// h2 lives in g_bufB.
__global__ void gbias_kernel(const int* __restrict__ sidx, const int* __restrict__ didx,
                             const float* __restrict__ ff_w,
                             const float* __restrict__ ff_b) {
    int b = blockIdx.x;            // 0..31
    int c = threadIdx.x;           // 0..127
    int srow = sidx[b] + b * N_PER;
    int drow = didx[b] + b * N_PER;
    const float* hs = g_bufB + srow * D;
    const float* hd = g_bufB + drow * D;
    float acc = ff_b[c];
    for (int k = 0; k < D; k++) {
        acc = fmaf(hs[k], ff_w[(D + k) * D + c], acc);
        acc = fmaf(hd[k], ff_w[(2 * D + k) * D + c], acc);
    }
    g_gbias[b * D + c] = acc;
}

// ---------------- batch-norm statistics (over g_bufC) ----------------
__global__ void bn_stats_kernel() {
    int col  = threadIdx.x & 127;
    int half = threadIdx.x >> 7;
    int rEnd = blockIdx.x * 256 + 256;
    float s = 0.0f, q = 0.0f;
    for (int r = blockIdx.x * 256 + half; r < rEnd; r += 2) {
        float v = g_bufC[r * D + col];
        s += v;
        q = fmaf(v, v, q);
    }
    atomicAdd(&g_sum[col], s);
    atomicAdd(&g_sumsq[col], q);
}

__global__ void bn_fin_kernel(const float* __restrict__ gamma, const float* __restrict__ beta) {
    int c = threadIdx.x;
    float inv_n = 1.0f / (float)N_NODES;
    float mean = g_sum[c] * inv_n;
    float var  = g_sumsq[c] * inv_n - mean * mean;
    float rstd = rsqrtf(var + 1e-5f);
    float sc = gamma[c] * rstd;
    g_scale[c] = sc;
    g_shift[c] = beta[c] - mean * sc;
}

// ---------------- final: [N,128]@[128,8] + bias + log_softmax --------------
// input rows live in g_bufA.
__global__ __launch_bounds__(256) void final_kernel(const float* __restrict__ w2,
                                                    const float* __restrict__ b2,
                                                    float* __restrict__ out) {
    __shared__ float W[D * C_OUT];
    __shared__ float bb[C_OUT];
    int tid = threadIdx.x;
    for (int i = tid; i < D * C_OUT; i += 256) W[i] = w2[i];
    if (tid < C_OUT) bb[tid] = b2[tid];
    __syncthreads();

    int warp = tid >> 5, lane = tid & 31;
    int row = blockIdx.x * 8 + warp;
    const float* hr = g_bufA + row * D;
    float a[4];
#pragma unroll
    for (int t = 0; t < 4; t++) a[t] = hr[lane + t * 32];

    float acc[C_OUT];
#pragma unroll
    for (int c = 0; c < C_OUT; c++) {
        float s = 0.0f;
#pragma unroll
        for (int t = 0; t < 4; t++) s = fmaf(a[t], W[(lane + t * 32) * C_OUT + c], s);
        acc[c] = s;
    }
#pragma unroll
    for (int off = 16; off; off >>= 1)
#pragma unroll
        for (int c = 0; c < C_OUT; c++) acc[c] += __shfl_xor_sync(0xffffffffu, acc[c], off);

    if (lane == 0) {
        float m = -1e30f;
#pragma unroll
        for (int c = 0; c < C_OUT; c++) { acc[c] += bb[c]; m = fmaxf(m, acc[c]); }
        float se = 0.0f;
#pragma unroll
        for (int c = 0; c < C_OUT; c++) se += expf(acc[c] - m);
        float lse = logf(se) + m;
        float4* o4 = (float4*)(out + row * C_OUT);
        o4[0] = make_float4(acc[0] - lse, acc[1] - lse, acc[2] - lse, acc[3] - lse);
        o4[1] = make_float4(acc[4] - lse, acc[5] - lse, acc[6] - lse, acc[7] - lse);
    }
}

// ---------------- launch (kernel launches ONLY — graph-capture safe) -------
extern "C" void kernel_launch(void* const* d_in, const int* in_sizes, int n_in,
                              void* d_out, int out_size) {
    const float* x      = (const float*)d_in[0];
    const int*   ei     = (const int*)  d_in[1];
    const int*   sidx   = (const int*)  d_in[2];
    const int*   didx   = (const int*)  d_in[3];
    const float* emb_w  = (const float*)d_in[4];
    const float* emb_b  = (const float*)d_in[5];
    const float* gcn1_w = (const float*)d_in[6];
    const float* gcn1_b = (const float*)d_in[7];
    const float* gcn2_w = (const float*)d_in[8];
    const float* gcn2_b = (const float*)d_in[9];
    const float* bn_g   = (const float*)d_in[10];
    const float* bn_b   = (const float*)d_in[11];
    const float* ff_w   = (const float*)d_in[12];
    const float* ff_b   = (const float*)d_in[13];
    const float* ff1_w  = (const float*)d_in[14];
    const float* ff1_b  = (const float*)d_in[15];
    const float* ff2_w  = (const float*)d_in[16];
    const float* ff2_b  = (const float*)d_in[17];
    float* out = (float*)d_out;

    const int* src = ei;
    const int* dst = ei + E_EDGES;

    const int EW = (N_NODES * D) / 4 / 256;   // 8192 elementwise blocks
    const int GM = N_NODES / 128;             // 512 gemm blocks

    // degree + norm (also zeroes BN accumulators)
    deg_init_kernel<<<N_NODES / 256, 256>>>();
    deg_count_kernel<<<E_EDGES / 256, 256>>>(dst);
    dinv_kernel<<<N_NODES / 256, 256>>>();

    // embedding: h0 = x @ emb_w + emb_b                      -> bufA
    sgemm128<1, false, 0, 1><<<GM, 256>>>(x, emb_w, nullptr, emb_b);

    // GCN1: t = h0 @ W1 -> bufB ; scatter -> bufC ; h1 = relu(.+b1) -> bufA
    sgemm128<0, false, 1, 2><<<GM, 256>>>(nullptr, gcn1_w, nullptr, nullptr);
    scatter_init_kernel<2, 3><<<EW, 256>>>();
    scatter_edges_kernel<2, 3><<<E_EDGES / 8, 256>>>(src, dst);
    add_bias_kernel<true, 3, 1><<<EW, 256>>>(gcn1_b);

    // GCN2: t = h1 @ W2 -> bufB ; scatter -> bufC ; h2 = .+b2 -> bufB
    sgemm128<0, false, 1, 2><<<GM, 256>>>(nullptr, gcn2_w, nullptr, nullptr);
    scatter_init_kernel<2, 3><<<EW, 256>>>();
    scatter_edges_kernel<2, 3><<<E_EDGES / 8, 256>>>(src, dst);
    add_bias_kernel<false, 3, 2><<<EW, 256>>>(gcn2_b);

    // per-graph bias from gathered src/dest rows (folds 2/3 of ff_w GEMM away)
    gbias_kernel<<<BATCH, D>>>(sidx, didx, ff_w, ff_b);

    // h3 = h2 @ ff_w[0:128] + gbias[graph]                   -> bufC
    sgemm128<3, false, 2, 3><<<GM, 256>>>(nullptr, ff_w, nullptr, nullptr);

    // batch norm stats over bufC
    bn_stats_kernel<<<N_NODES / 256, 256>>>();
    bn_fin_kernel<<<1, D>>>(bn_g, bn_b);

    // h5 = relu( bn_relu(h3) @ ff1_w + ff1_b )               -> bufA
    sgemm128<2, true, 3, 1><<<GM, 256>>>(nullptr, ff1_w, nullptr, ff1_b);

    // logits + log_softmax
    final_kernel<<<N_NODES / 8, 256>>>(ff2_w, ff2_b, out);
}

// round 5
// speedup vs baseline: 1.3261x; 1.3261x over previous
#include <cuda_runtime.h>
#include <cuda_bf16.h>

#define N_NODES 65536
#define N_PER   2048
#define BATCH   32
#define E_EDGES 1048576
#define D       128
#define C_OUT   8

typedef unsigned long long ull;

// ---------------- scratch (device globals: allocation-free) ----------------
__device__ float g_bufA[N_NODES * D];
__device__ float g_bufB[N_NODES * D];
__device__ float g_bufC[N_NODES * D];
__device__ float g_deg[N_NODES];
__device__ float g_dinv[N_NODES];
__device__ float g_gbias[BATCH * D];
__device__ float g_sum[D];
__device__ float g_sumsq[D];
__device__ float g_scale[D];
__device__ float g_shift[D];
__device__ float g_wp[D * D];   // emb_w @ gcn1_w
__device__ float g_bp[D];       // emb_b @ gcn1_w

__device__ __forceinline__ float* buf_ptr_dev(int sel) {
    switch (sel) {
        case 1: return g_bufA;
        case 2: return g_bufB;
        default: return g_bufC;
    }
}

// ---------------- packed f32x2 helpers (Blackwell) ----------------
__device__ __forceinline__ void ffma2(ull& d, ull a, ull b) {
    asm("fma.rn.f32x2 %0, %1, %2, %0;" : "+l"(d) : "l"(a), "l"(b));
}
__device__ __forceinline__ ull pack2(float x, float y) {
    ull r; asm("mov.b64 %0, {%1, %2};" : "=l"(r) : "f"(x), "f"(y)); return r;
}
__device__ __forceinline__ ull dup2(float x) {
    ull r; asm("mov.b64 %0, {%1, %1};" : "=l"(r) : "f"(x)); return r;
}
__device__ __forceinline__ float2 unpack2(ull v) {
    float2 r; asm("mov.b64 {%0, %1}, %2;" : "=f"(r.x), "=f"(r.y) : "l"(v)); return r;
}

__device__ __forceinline__ void atomic_add_f4(float4* addr, float4 v) {
    asm volatile("red.global.add.v4.f32 [%0], {%1,%2,%3,%4};"
                 :: "l"(addr), "f"(v.x), "f"(v.y), "f"(v.z), "f"(v.w) : "memory");
}

// ---------------- degree / norm ----------------
__global__ void deg_init_kernel() {
    int i = blockIdx.x * 256 + threadIdx.x;
    if (i < N_NODES) g_deg[i] = 1.0f;      // self-loop
    if (i < D) { g_sum[i] = 0.0f; g_sumsq[i] = 0.0f; }
}

__global__ void deg_count_kernel(const int* __restrict__ dst) {
    int e = blockIdx.x * 256 + threadIdx.x;
    if (e < E_EDGES) atomicAdd(&g_deg[dst[e]], 1.0f);
}

__global__ void dinv_kernel() {
    int i = blockIdx.x * 256 + threadIdx.x;
    if (i < N_NODES) g_dinv[i] = rsqrtf(g_deg[i]);
}

// ---------------- weight prefold: g_wp = emb_w@gcn1_w, g_bp = emb_b@gcn1_w --
__global__ void prep_w_kernel(const float* __restrict__ emb_w,
                              const float* __restrict__ emb_b,
                              const float* __restrict__ gcn1_w) {
    __shared__ float arow[D];
    int r = blockIdx.x;           // 0..128 (128 = bias row)
    int c = threadIdx.x;          // 0..127
    arow[c] = (r < D) ? emb_w[r * D + c] : emb_b[c];
    __syncthreads();
    float acc = 0.0f;
#pragma unroll 8
    for (int k = 0; k < D; k++) acc = fmaf(arow[k], gcn1_w[k * D + c], acc);
    if (r < D) g_wp[r * D + c] = acc;
    else       g_bp[c] = acc;
}

// ---------------- packed-FMA GEMM: C[M,128] = f(A)[M,128] @ B[128,128] -----
// ATR (A-load transform): 0 none, 1 relu(a+avec[k]), 2 relu(a*g_scale[k]+g_shift[k])
// EPI: 0 none, 1 +bias[col], 2 relu(+bias[col]), 3 +g_gbias[graph][col]
// SCAT: also write C2[row] = dinv[row]^2 * stored C value
// BNST: accumulate per-column sum/sumsq of stored C into g_sum/g_sumsq
// ASEL/CSEL/C2SEL: 0 ext (A only), else g_buf A/B/C.  BSEL: 0 ext, 1 g_wp.  BIASSEL: 0 ext, 1 g_bp.
template<int ATR, int EPI, bool SCAT, bool BNST, int ASEL, int CSEL, int C2SEL, int BSEL, int BIASSEL>
__global__ __launch_bounds__(256, 2) void sgemm128p(const float* __restrict__ Aext,
                                                    const float* __restrict__ Bext,
                                                    const float* __restrict__ biasext,
                                                    const float* __restrict__ avec) {
    const float* A    = (ASEL == 0) ? Aext : buf_ptr_dev(ASEL);
    const float* B    = (BSEL == 0) ? Bext : g_wp;
    const float* bias = (BIASSEL == 0) ? biasext : g_bp;
    float* Cm = buf_ptr_dev(CSEL);
    float* C2 = buf_ptr_dev(C2SEL);

    __shared__ float As[16][128];
    __shared__ float Bs[16][128];
    const int tid = threadIdx.x;
    const int tr = tid >> 4;          // 0..15
    const int tc = tid & 15;          // 0..15
    const int rowBase = blockIdx.x * 128;

    ull acc[4][8];
#pragma unroll
    for (int p = 0; p < 4; p++)
#pragma unroll
        for (int j = 0; j < 8; j++) acc[p][j] = 0ull;

    for (int k0 = 0; k0 < 128; k0 += 16) {
#pragma unroll
        for (int s = 0; s < 2; s++) {
            int id = tid * 2 + s;                    // 0..511
            int ar = id >> 2;
            int ak = (id & 3) * 4;
            float4 av = *(const float4*)(A + (rowBase + ar) * D + k0 + ak);
            if (ATR == 1) {
                av.x = fmaxf(av.x + avec[k0 + ak + 0], 0.0f);
                av.y = fmaxf(av.y + avec[k0 + ak + 1], 0.0f);
                av.z = fmaxf(av.z + avec[k0 + ak + 2], 0.0f);
                av.w = fmaxf(av.w + avec[k0 + ak + 3], 0.0f);
            } else if (ATR == 2) {
                av.x = fmaxf(fmaf(av.x, g_scale[k0 + ak + 0], g_shift[k0 + ak + 0]), 0.0f);
                av.y = fmaxf(fmaf(av.y, g_scale[k0 + ak + 1], g_shift[k0 + ak + 1]), 0.0f);
                av.z = fmaxf(fmaf(av.z, g_scale[k0 + ak + 2], g_shift[k0 + ak + 2]), 0.0f);
                av.w = fmaxf(fmaf(av.w, g_scale[k0 + ak + 3], g_shift[k0 + ak + 3]), 0.0f);
            }
            As[ak + 0][ar] = av.x;
            As[ak + 1][ar] = av.y;
            As[ak + 2][ar] = av.z;
            As[ak + 3][ar] = av.w;
            int br = id >> 5;
            int bc = (id & 31) * 4;
            *(float4*)&Bs[br][bc] = *(const float4*)(B + (k0 + br) * D + bc);
        }
        __syncthreads();
#pragma unroll
        for (int kk = 0; kk < 16; kk++) {
            float4 a0 = *(const float4*)&As[kk][tr * 8];
            float4 a1 = *(const float4*)&As[kk][tr * 8 + 4];
            float4 b0 = *(const float4*)&Bs[kk][tc * 8];
            float4 b1 = *(const float4*)&Bs[kk][tc * 8 + 4];
            ull ap0 = pack2(a0.x, a0.y);
            ull ap1 = pack2(a0.z, a0.w);
            ull ap2 = pack2(a1.x, a1.y);
            ull ap3 = pack2(a1.z, a1.w);
            // hoist all broadcasts (alu pipe) ahead of the FMA burst
            ull bd[8];
            bd[0] = dup2(b0.x); bd[1] = dup2(b0.y); bd[2] = dup2(b0.z); bd[3] = dup2(b0.w);
            bd[4] = dup2(b1.x); bd[5] = dup2(b1.y); bd[6] = dup2(b1.z); bd[7] = dup2(b1.w);
#pragma unroll
            for (int j = 0; j < 8; j++) {
                ffma2(acc[0][j], ap0, bd[j]);
                ffma2(acc[1][j], ap1, bd[j]);
                ffma2(acc[2][j], ap2, bd[j]);
                ffma2(acc[3][j], ap3, bd[j]);
            }
        }
        __syncthreads();
    }

    // ---- epilogue ----
    float bcol[8];
    if (EPI == 1 || EPI == 2) {
#pragma unroll
        for (int j = 0; j < 8; j++) bcol[j] = bias[tc * 8 + j];
    } else if (EPI == 3) {
        const float* brow = g_gbias + (rowBase >> 11) * D;  // graph per 2048-row block
#pragma unroll
        for (int j = 0; j < 8; j++) bcol[j] = brow[tc * 8 + j];
    }

    float ps[8], pq[8];
    if (BNST) {
#pragma unroll
        for (int j = 0; j < 8; j++) { ps[j] = 0.0f; pq[j] = 0.0f; }
    }

#pragma unroll
    for (int p = 0; p < 4; p++) {
        int r0 = rowBase + tr * 8 + 2 * p;
        float x0[8], x1[8];
#pragma unroll
        for (int j = 0; j < 8; j++) {
            float2 v = unpack2(acc[p][j]);
            float a = v.x, b = v.y;
            if (EPI >= 1) { a += bcol[j]; b += bcol[j]; }
            if (EPI == 2) { a = fmaxf(a, 0.0f); b = fmaxf(b, 0.0f); }
            x0[j] = a; x1[j] = b;
        }
        *(float4*)(Cm + r0 * D + tc * 8)           = make_float4(x0[0], x0[1], x0[2], x0[3]);
        *(float4*)(Cm + r0 * D + tc * 8 + 4)       = make_float4(x0[4], x0[5], x0[6], x0[7]);
        *(float4*)(Cm + (r0 + 1) * D + tc * 8)     = make_float4(x1[0], x1[1], x1[2], x1[3]);
        *(float4*)(Cm + (r0 + 1) * D + tc * 8 + 4) = make_float4(x1[4], x1[5], x1[6], x1[7]);
        if (SCAT) {
            float d0 = g_dinv[r0];     float n0 = d0 * d0;
            float d1 = g_dinv[r0 + 1]; float n1 = d1 * d1;
            *(float4*)(C2 + r0 * D + tc * 8)           = make_float4(x0[0]*n0, x0[1]*n0, x0[2]*n0, x0[3]*n0);
            *(float4*)(C2 + r0 * D + tc * 8 + 4)       = make_float4(x0[4]*n0, x0[5]*n0, x0[6]*n0, x0[7]*n0);
            *(float4*)(C2 + (r0 + 1) * D + tc * 8)     = make_float4(x1[0]*n1, x1[1]*n1, x1[2]*n1, x1[3]*n1);
            *(float4*)(C2 + (r0 + 1) * D + tc * 8 + 4) = make_float4(x1[4]*n1, x1[5]*n1, x1[6]*n1, x1[7]*n1);
        }
        if (BNST) {
#pragma unroll
            for (int j = 0; j < 8; j++) {
                ps[j] += x0[j] + x1[j];
                pq[j] = fmaf(x0[j], x0[j], pq[j]);
                pq[j] = fmaf(x1[j], x1[j], pq[j]);
            }
        }
    }

    if (BNST) {
        __syncthreads();
#pragma unroll
        for (int j = 0; j < 8; j++) As[tr][tc * 8 + j] = ps[j];
        __syncthreads();
        if (tid < 128) {
            float s = 0.0f;
#pragma unroll
            for (int t = 0; t < 16; t++) s += As[t][tid];
            atomicAdd(&g_sum[tid], s);
        }
        __syncthreads();
#pragma unroll
        for (int j = 0; j < 8; j++) As[tr][tc * 8 + j] = pq[j];
        __syncthreads();
        if (tid < 128) {
            float q = 0.0f;
#pragma unroll
            for (int t = 0; t < 16; t++) q += As[t][tid];
            atomicAdd(&g_sumsq[tid], q);
        }
    }
}

// ---------------- edge scatter: acc[dst] += dinv[s]*dinv[d]*t[src] ---------
template<int TSEL, int OSEL>
__global__ __launch_bounds__(256) void scatter_edges_kernel(const int* __restrict__ src,
                                                            const int* __restrict__ dst) {
    const float* t = buf_ptr_dev(TSEL);
    float* acc = buf_ptr_dev(OSEL);
    int e = blockIdx.x * 8 + (threadIdx.x >> 5);
    int lane = threadIdx.x & 31;
    int s = src[e];
    int d = dst[e];
    float nrm = g_dinv[s] * g_dinv[d];
    float4 v = ((const float4*)(t + s * D))[lane];
    v.x *= nrm; v.y *= nrm; v.z *= nrm; v.w *= nrm;
    atomic_add_f4(((float4*)(acc + d * D)) + lane, v);
}

// ---------------- per-graph bias (folds ff_b + b2@Wf + src/dest terms) -----
// h2 = g_bufC(acc2) + gcn2_b ;  gbias[b][c] = ff_b[c] + sum_k b2[k]*Wf[k][c]
//                               + sum_k h2[srow][k]*Wf[D+k][c] + h2[drow][k]*Wf[2D+k][c]
__global__ void gbias_kernel(const int* __restrict__ sidx, const int* __restrict__ didx,
                             const float* __restrict__ ff_w, const float* __restrict__ ff_b,
                             const float* __restrict__ gcn2_b) {
    int b = blockIdx.x;            // 0..31
    int c = threadIdx.x;           // 0..127
    int srow = sidx[b] + b * N_PER;
    int drow = didx[b] + b * N_PER;
    const float* hs = g_bufC + srow * D;
    const float* hd = g_bufC + drow * D;
    float acc = ff_b[c];
    for (int k = 0; k < D; k++) {
        float b2 = gcn2_b[k];
        acc = fmaf(b2,          ff_w[k * D + c],           acc);
        acc = fmaf(hs[k] + b2,  ff_w[(D + k) * D + c],     acc);
        acc = fmaf(hd[k] + b2,  ff_w[(2 * D + k) * D + c], acc);
    }
    g_gbias[b * D + c] = acc;
}

// ---------------- batch-norm finalize ----------------
__global__ void bn_fin_kernel(const float* __restrict__ gamma, const float* __restrict__ beta) {
    int c = threadIdx.x;
    float inv_n = 1.0f / (float)N_NODES;
    float mean = g_sum[c] * inv_n;
    float var  = g_sumsq[c] * inv_n - mean * mean;
    float rstd = rsqrtf(var + 1e-5f);
    float sc = gamma[c] * rstd;
    g_scale[c] = sc;
    g_shift[c] = beta[c] - mean * sc;
}

// ---------------- final: [N,128]@[128,8] + bias + log_softmax --------------
// input rows live in g_bufB (h5).
__global__ __launch_bounds__(256) void final_kernel(const float* __restrict__ w2,
                                                    const float* __restrict__ b2,
                                                    float* __restrict__ out) {
    __shared__ float W[D * C_OUT];
    __shared__ float bb[C_OUT];
    int tid = threadIdx.x;
    for (int i = tid; i < D * C_OUT; i += 256) W[i] = w2[i];
    if (tid < C_OUT) bb[tid] = b2[tid];
    __syncthreads();

    int warp = tid >> 5, lane = tid & 31;
    int row = blockIdx.x * 8 + warp;
    const float* hr = g_bufB + row * D;
    float a[4];
#pragma unroll
    for (int t = 0; t < 4; t++) a[t] = hr[lane + t * 32];

    float acc[C_OUT];
#pragma unroll
    for (int c = 0; c < C_OUT; c++) {
        float s = 0.0f;
#pragma unroll
        for (int t = 0; t < 4; t++) s = fmaf(a[t], W[(lane + t * 32) * C_OUT + c], s);
        acc[c] = s;
    }
#pragma unroll
    for (int off = 16; off; off >>= 1)
#pragma unroll
        for (int c = 0; c < C_OUT; c++) acc[c] += __shfl_xor_sync(0xffffffffu, acc[c], off);

    if (lane == 0) {
        float m = -1e30f;
#pragma unroll
        for (int c = 0; c < C_OUT; c++) { acc[c] += bb[c]; m = fmaxf(m, acc[c]); }
        float se = 0.0f;
#pragma unroll
        for (int c = 0; c < C_OUT; c++) se += expf(acc[c] - m);
        float lse = logf(se) + m;
        float4* o4 = (float4*)(out + row * C_OUT);
        o4[0] = make_float4(acc[0] - lse, acc[1] - lse, acc[2] - lse, acc[3] - lse);
        o4[1] = make_float4(acc[4] - lse, acc[5] - lse, acc[6] - lse, acc[7] - lse);
    }
}

// ---------------- launch (kernel launches ONLY — graph-capture safe) -------
extern "C" void kernel_launch(void* const* d_in, const int* in_sizes, int n_in,
                              void* d_out, int out_size) {
    const float* x      = (const float*)d_in[0];
    const int*   ei     = (const int*)  d_in[1];
    const int*   sidx   = (const int*)  d_in[2];
    const int*   didx   = (const int*)  d_in[3];
    const float* emb_w  = (const float*)d_in[4];
    const float* emb_b  = (const float*)d_in[5];
    const float* gcn1_w = (const float*)d_in[6];
    const float* gcn1_b = (const float*)d_in[7];
    const float* gcn2_w = (const float*)d_in[8];
    const float* gcn2_b = (const float*)d_in[9];
    const float* bn_g   = (const float*)d_in[10];
    const float* bn_b   = (const float*)d_in[11];
    const float* ff_w   = (const float*)d_in[12];
    const float* ff_b   = (const float*)d_in[13];
    const float* ff1_w  = (const float*)d_in[14];
    const float* ff1_b  = (const float*)d_in[15];
    const float* ff2_w  = (const float*)d_in[16];
    const float* ff2_b  = (const float*)d_in[17];
    float* out = (float*)d_out;

    const int* src = ei;
    const int* dst = ei + E_EDGES;
    const int GM = N_NODES / 128;             // 512 gemm blocks

    // degree + norm (also zeroes BN accumulators); weight prefold
    deg_init_kernel<<<N_NODES / 256, 256>>>();
    deg_count_kernel<<<E_EDGES / 256, 256>>>(dst);
    dinv_kernel<<<N_NODES / 256, 256>>>();
    prep_w_kernel<<<D + 1, D>>>(emb_w, emb_b, gcn1_w);

    // GCN1: t1 = x@(We W1) + (be W1) -> bufB ; self-loop init dinv^2*t1 -> bufC
    sgemm128p<0, 1, true, false, 0, 2, 3, 1, 1><<<GM, 256>>>(x, nullptr, nullptr, nullptr);
    scatter_edges_kernel<2, 3><<<E_EDGES / 8, 256>>>(src, dst);   // acc1 -> bufC

    // GCN2: A = relu(acc1 + b1) (in-place-safe), t2 -> bufB, dinv^2*t2 -> bufC
    sgemm128p<1, 0, true, false, 3, 2, 3, 0, 0><<<GM, 256>>>(nullptr, gcn2_w, nullptr, gcn1_b);
    scatter_edges_kernel<2, 3><<<E_EDGES / 8, 256>>>(src, dst);   // acc2 -> bufC

    // per-graph bias: ff_b + b2@Wf + src/dest gathered terms
    gbias_kernel<<<BATCH, D>>>(sidx, didx, ff_w, ff_b, gcn2_b);

    // ff: h3 = acc2 @ Wf[0:128] + gbias[graph] -> bufA ; BN stats fused
    sgemm128p<0, 3, false, true, 3, 1, 3, 0, 0><<<GM, 256>>>(nullptr, ff_w, nullptr, nullptr);
    bn_fin_kernel<<<1, D>>>(bn_g, bn_b);

    // ff1: h5 = relu( bnrelu(h3) @ W1f + b1f ) -> bufB
    sgemm128p<2, 2, false, false, 1, 2, 3, 0, 0><<<GM, 256>>>(nullptr, ff1_w, ff1_b, nullptr);

    // logits + log_softmax
    final_kernel<<<N_NODES / 8, 256>>>(ff2_w, ff2_b, out);
}

// round 8
// speedup vs baseline: 1.6064x; 1.2113x over previous
#include <cuda_runtime.h>
#include <cuda_bf16.h>
#include <cstdint>

#define N_NODES 65536
#define N_PER   2048
#define BATCH   32
#define E_EDGES 1048576
#define D       128
#define C_OUT   8

// ---------------- scratch (device globals: allocation-free) ----------------
__device__ float g_bufA[N_NODES * D];
__device__ float g_bufB[N_NODES * D];
__device__ float g_bufC[N_NODES * D];
__device__ float g_deg[N_NODES];
__device__ float g_dinv[N_NODES];
__device__ float g_gbias[BATCH * D];
__device__ float g_sum[D];
__device__ float g_sumsq[D];
__device__ float g_scale[D];
__device__ float g_shift[D];
__device__ float g_wp[D * D];   // emb_w @ gcn1_w
__device__ float g_bp[D];       // emb_b @ gcn1_w
// pre-packed B fragments for mma.sync: [img][kt(8)][nt(16)][lane(32)] uint2
__device__ uint2 g_bfragH[4 * 8 * 16 * 32];
__device__ uint2 g_bfragL[4 * 8 * 16 * 32];

__device__ __forceinline__ float* buf_ptr_dev(int sel) {
    switch (sel) {
        case 1: return g_bufA;
        case 2: return g_bufB;
        default: return g_bufC;
    }
}

// ---------------- helpers ----------------
__device__ __forceinline__ void mma_bf16(float c[4], uint32_t a0, uint32_t a1,
                                         uint32_t a2, uint32_t a3,
                                         uint32_t b0, uint32_t b1) {
    asm volatile(
        "mma.sync.aligned.m16n8k16.row.col.f32.bf16.bf16.f32 "
        "{%0,%1,%2,%3}, {%4,%5,%6,%7}, {%8,%9}, {%0,%1,%2,%3};"
        : "+f"(c[0]), "+f"(c[1]), "+f"(c[2]), "+f"(c[3])
        : "r"(a0), "r"(a1), "r"(a2), "r"(a3), "r"(b0), "r"(b1));
}
__device__ __forceinline__ uint32_t pack_bf16x2(float lo, float hi) {
    __nv_bfloat162 h = __floats2bfloat162_rn(lo, hi);   // .x=lo(low half), .y=hi
    return *(uint32_t*)&h;
}
__device__ __forceinline__ void split2(float v0, float v1, uint32_t& h, uint32_t& l) {
    __nv_bfloat16 h0 = __float2bfloat16(v0);
    __nv_bfloat16 h1 = __float2bfloat16(v1);
    float r0 = v0 - __bfloat162float(h0);
    float r1 = v1 - __bfloat162float(h1);
    __nv_bfloat162 hp; hp.x = h0; hp.y = h1;
    h = *(uint32_t*)&hp;
    l = pack_bf16x2(r0, r1);
}
__device__ __forceinline__ void atomic_add_f4(float4* addr, float4 v) {
    asm volatile("red.global.add.v4.f32 [%0], {%1,%2,%3,%4};"
                 :: "l"(addr), "f"(v.x), "f"(v.y), "f"(v.z), "f"(v.w) : "memory");
}

// ---------------- degree / norm ----------------
__global__ void deg_init_kernel() {
    int i = blockIdx.x * 256 + threadIdx.x;
    if (i < N_NODES) g_deg[i] = 1.0f;      // self-loop
    if (i < D) { g_sum[i] = 0.0f; g_sumsq[i] = 0.0f; }
}
__global__ void deg_count_kernel(const int* __restrict__ dst) {
    int e = blockIdx.x * 256 + threadIdx.x;
    if (e < E_EDGES) atomicAdd(&g_deg[dst[e]], 1.0f);
}
__global__ void dinv_kernel() {
    int i = blockIdx.x * 256 + threadIdx.x;
    if (i < N_NODES) g_dinv[i] = rsqrtf(g_deg[i]);
}

// ---------------- weight prefold: g_wp = emb_w@gcn1_w, g_bp = emb_b@gcn1_w --
__global__ void prep_w_kernel(const float* __restrict__ emb_w,
                              const float* __restrict__ emb_b,
                              const float* __restrict__ gcn1_w) {
    __shared__ float arow[D];
    int r = blockIdx.x;           // 0..128 (128 = bias row)
    int c = threadIdx.x;          // 0..127
    arow[c] = (r < D) ? emb_w[r * D + c] : emb_b[c];
    __syncthreads();
    float acc = 0.0f;
#pragma unroll 8
    for (int k = 0; k < D; k++) acc = fmaf(arow[k], gcn1_w[k * D + c], acc);
    if (r < D) g_wp[r * D + c] = acc;
    else       g_bp[c] = acc;
}

// ---------------- B fragment prep ----------------
// mma B frag (16k x 8n, col-major): thread(lane): g=lane>>2, t=lane&3
//   reg0 = { B[2t][g],   B[2t+1][g] }   reg1 = { B[2t+8][g], B[2t+9][g] }
// B[k][n] = W[k][n].  Index: ((img*8+kt)*16+nt)*32+lane
__global__ void prep_bfrag_kernel(const float* __restrict__ gcn2_w,
                                  const float* __restrict__ ff_w,
                                  const float* __restrict__ ff1_w) {
    int idx  = blockIdx.x * 256 + threadIdx.x;   // 0..16383
    int lane = idx & 31;
    int nt   = (idx >> 5) & 15;
    int kt   = (idx >> 9) & 7;
    int img  = idx >> 12;
    int g = lane >> 2, t = lane & 3;
    const float* W;
    if      (img == 0) W = g_wp;
    else if (img == 1) W = gcn2_w;
    else if (img == 2) W = ff_w;     // rows 0..127 only
    else               W = ff1_w;
    int n = nt * 8 + g;
    int k0 = kt * 16 + 2 * t;
    float w00 = W[(k0)     * D + n], w01 = W[(k0 + 1) * D + n];
    float w10 = W[(k0 + 8) * D + n], w11 = W[(k0 + 9) * D + n];
    uint32_t h0, l0, h1, l1;
    split2(w00, w01, h0, l0);
    split2(w10, w11, h1, l1);
    g_bfragH[idx] = make_uint2(h0, h1);
    g_bfragL[idx] = make_uint2(l0, l1);
}

// ---------------- mma.sync split-bf16 GEMM: C = f(A) @ W (+epilogue) -------
// ATR: 0 none, 1 relu(a+avec[k]), 2 relu(a*g_scale+g_shift)
// EPI: 0 none, 1 +bias, 2 relu(+bias), 3 +g_gbias[graph]
// SCAT: also C2[row] = dinv[row]^2 * stored value
// BIASSEL: 0 = biasext, 1 = g_bp (prefolded embedding bias)
#define AS_STRIDE 68   // bf16 elements per row (64 data + 4 pad)

template<int ATR, int EPI, bool SCAT, int ASEL, int CSEL, int C2SEL, int IMG, int BIASSEL>
__global__ __launch_bounds__(256) void tcgemm(const float* __restrict__ Aext,
                                              const float* __restrict__ biasext,
                                              const float* __restrict__ avec) {
    __shared__ __align__(16) __nv_bfloat16 AsH[128 * AS_STRIDE];
    __shared__ __align__(16) __nv_bfloat16 AsL[128 * AS_STRIDE];
    __shared__ float sbias[D];

    const float* A = (ASEL == 0) ? Aext : buf_ptr_dev(ASEL);
    const float* bias = (BIASSEL == 0) ? biasext : g_bp;   // FIX: R6/R7 dropped this dispatch
    float* Cm = buf_ptr_dev(CSEL);
    float* C2 = buf_ptr_dev(C2SEL);

    const int tid = threadIdx.x;
    const int wid = tid >> 5, lane = tid & 31;
    const int warpM = wid >> 1, warpN = wid & 1;
    const int g = lane >> 2, t = lane & 3;
    const int rowBase = blockIdx.x * 128;

    if (tid < D) {
        if (EPI == 1 || EPI == 2)      sbias[tid] = bias[tid];
        else if (EPI == 3)             sbias[tid] = g_gbias[(rowBase >> 11) * D + tid];
        else                           sbias[tid] = 0.0f;
    }

    float c[2][8][4];
#pragma unroll
    for (int m = 0; m < 2; m++)
#pragma unroll
        for (int n = 0; n < 8; n++)
#pragma unroll
            for (int q = 0; q < 4; q++) c[m][n][q] = 0.0f;

    for (int ch = 0; ch < 2; ch++) {
        __syncthreads();
        // stage 128 rows x 64 k-cols (f32 -> bf16 hi/lo), transformed
#pragma unroll
        for (int i = 0; i < 8; i++) {
            int e = tid + i * 256;                 // float4 id, 0..2047
            int row = e >> 4;
            int cp  = (e & 15) * 4;                // local col 0..60
            int col = ch * 64 + cp;
            float4 v = *(const float4*)(A + (size_t)(rowBase + row) * D + col);
            if (ATR == 1) {
                v.x = fmaxf(v.x + avec[col + 0], 0.0f);
                v.y = fmaxf(v.y + avec[col + 1], 0.0f);
                v.z = fmaxf(v.z + avec[col + 2], 0.0f);
                v.w = fmaxf(v.w + avec[col + 3], 0.0f);
            } else if (ATR == 2) {
                v.x = fmaxf(fmaf(v.x, g_scale[col + 0], g_shift[col + 0]), 0.0f);
                v.y = fmaxf(fmaf(v.y, g_scale[col + 1], g_shift[col + 1]), 0.0f);
                v.z = fmaxf(fmaf(v.z, g_scale[col + 2], g_shift[col + 2]), 0.0f);
                v.w = fmaxf(fmaf(v.w, g_scale[col + 3], g_shift[col + 3]), 0.0f);
            }
            uint32_t h0, l0, h1, l1;
            split2(v.x, v.y, h0, l0);
            split2(v.z, v.w, h1, l1);
            *(uint2*)&AsH[row * AS_STRIDE + cp] = make_uint2(h0, h1);
            *(uint2*)&AsL[row * AS_STRIDE + cp] = make_uint2(l0, l1);
        }
        __syncthreads();

#pragma unroll
        for (int kt = 0; kt < 4; kt++) {
            int ktg = ch * 4 + kt;
            // A fragments (both m-tiles, hi+lo)
            uint32_t aH[2][4], aL[2][4];
#pragma unroll
            for (int m = 0; m < 2; m++) {
                int r0 = warpM * 32 + m * 16 + g;
                int r1 = r0 + 8;
                int cb = kt * 16 + 2 * t;
                aH[m][0] = *(const uint32_t*)&AsH[r0 * AS_STRIDE + cb];
                aH[m][1] = *(const uint32_t*)&AsH[r1 * AS_STRIDE + cb];
                aH[m][2] = *(const uint32_t*)&AsH[r0 * AS_STRIDE + cb + 8];
                aH[m][3] = *(const uint32_t*)&AsH[r1 * AS_STRIDE + cb + 8];
                aL[m][0] = *(const uint32_t*)&AsL[r0 * AS_STRIDE + cb];
                aL[m][1] = *(const uint32_t*)&AsL[r1 * AS_STRIDE + cb];
                aL[m][2] = *(const uint32_t*)&AsL[r0 * AS_STRIDE + cb + 8];
                aL[m][3] = *(const uint32_t*)&AsL[r1 * AS_STRIDE + cb + 8];
            }
            const uint2* bh = g_bfragH + ((size_t)(IMG * 8 + ktg) * 16 + warpN * 8) * 32 + lane;
            const uint2* bl = g_bfragL + ((size_t)(IMG * 8 + ktg) * 16 + warpN * 8) * 32 + lane;
#pragma unroll
            for (int nt = 0; nt < 8; nt++) {
                uint2 bH = bh[nt * 32];
                uint2 bL = bl[nt * 32];
#pragma unroll
                for (int m = 0; m < 2; m++) {
                    mma_bf16(c[m][nt], aH[m][0], aH[m][1], aH[m][2], aH[m][3], bH.x, bH.y);
                    mma_bf16(c[m][nt], aH[m][0], aH[m][1], aH[m][2], aH[m][3], bL.x, bL.y);
                    mma_bf16(c[m][nt], aL[m][0], aL[m][1], aL[m][2], aL[m][3], bH.x, bH.y);
                }
            }
        }
    }

    // ---- epilogue ----
#pragma unroll
    for (int m = 0; m < 2; m++) {
        int r0 = rowBase + warpM * 32 + m * 16 + g;
        int r1 = r0 + 8;
        float dv0 = 0.0f, dv1 = 0.0f;
        if (SCAT) {
            float a = g_dinv[r0]; dv0 = a * a;
            float b = g_dinv[r1]; dv1 = b * b;
        }
#pragma unroll
        for (int nt = 0; nt < 8; nt++) {
            int cn = warpN * 64 + nt * 8 + 2 * t;
            float v0 = c[m][nt][0], v1 = c[m][nt][1];
            float v2 = c[m][nt][2], v3 = c[m][nt][3];
            if (EPI >= 1) {
                float b0 = sbias[cn], b1 = sbias[cn + 1];
                v0 += b0; v1 += b1; v2 += b0; v3 += b1;
            }
            if (EPI == 2) {
                v0 = fmaxf(v0, 0.0f); v1 = fmaxf(v1, 0.0f);
                v2 = fmaxf(v2, 0.0f); v3 = fmaxf(v3, 0.0f);
            }
            *(float2*)(Cm + (size_t)r0 * D + cn) = make_float2(v0, v1);
            *(float2*)(Cm + (size_t)r1 * D + cn) = make_float2(v2, v3);
            if (SCAT) {
                *(float2*)(C2 + (size_t)r0 * D + cn) = make_float2(v0 * dv0, v1 * dv0);
                *(float2*)(C2 + (size_t)r1 * D + cn) = make_float2(v2 * dv1, v3 * dv1);
            }
        }
    }
}

// ---------------- edge scatter: acc[dst] += dinv[s]*dinv[d]*t[src] ---------
template<int TSEL, int OSEL>
__global__ __launch_bounds__(256) void scatter_edges_kernel(const int* __restrict__ src,
                                                            const int* __restrict__ dst) {
    const float* t = buf_ptr_dev(TSEL);
    float* acc = buf_ptr_dev(OSEL);
    int e = blockIdx.x * 8 + (threadIdx.x >> 5);
    int lane = threadIdx.x & 31;
    int s = src[e];
    int d = dst[e];
    float nrm = g_dinv[s] * g_dinv[d];
    float4 v = ((const float4*)(t + (size_t)s * D))[lane];
    v.x *= nrm; v.y *= nrm; v.z *= nrm; v.w *= nrm;
    atomic_add_f4(((float4*)(acc + (size_t)d * D)) + lane, v);
}

// ---------------- per-graph bias ----------------
__global__ void gbias_kernel(const int* __restrict__ sidx, const int* __restrict__ didx,
                             const float* __restrict__ ff_w, const float* __restrict__ ff_b,
                             const float* __restrict__ gcn2_b) {
    int b = blockIdx.x;
    int c = threadIdx.x;
    int srow = sidx[b] + b * N_PER;
    int drow = didx[b] + b * N_PER;
    const float* hs = g_bufC + (size_t)srow * D;
    const float* hd = g_bufC + (size_t)drow * D;
    float acc = ff_b[c];
    for (int k = 0; k < D; k++) {
        float b2 = gcn2_b[k];
        acc = fmaf(b2,         ff_w[k * D + c],           acc);
        acc = fmaf(hs[k] + b2, ff_w[(D + k) * D + c],     acc);
        acc = fmaf(hd[k] + b2, ff_w[(2 * D + k) * D + c], acc);
    }
    g_gbias[b * D + c] = acc;
}

// ---------------- batch-norm stats / finalize ----------------
template<int SEL>
__global__ void bn_stats_kernel() {
    const float* h = buf_ptr_dev(SEL);
    int col  = threadIdx.x & 127;
    int half = threadIdx.x >> 7;
    int rEnd = blockIdx.x * 256 + 256;
    float s = 0.0f, q = 0.0f;
    for (int r = blockIdx.x * 256 + half; r < rEnd; r += 2) {
        float v = h[(size_t)r * D + col];
        s += v;
        q = fmaf(v, v, q);
    }
    atomicAdd(&g_sum[col], s);
    atomicAdd(&g_sumsq[col], q);
}
__global__ void bn_fin_kernel(const float* __restrict__ gamma, const float* __restrict__ beta) {
    int c = threadIdx.x;
    float inv_n = 1.0f / (float)N_NODES;
    float mean = g_sum[c] * inv_n;
    float var  = g_sumsq[c] * inv_n - mean * mean;
    float rstd = rsqrtf(var + 1e-5f);
    float sc = gamma[c] * rstd;
    g_scale[c] = sc;
    g_shift[c] = beta[c] - mean * sc;
}

// ---------------- final: [N,128]@[128,8] + bias + log_softmax --------------
__global__ __launch_bounds__(256) void final_kernel(const float* __restrict__ w2,
                                                    const float* __restrict__ b2,
                                                    float* __restrict__ out) {
    __shared__ float W[D * C_OUT];
    __shared__ float bb[C_OUT];
    int tid = threadIdx.x;
    for (int i = tid; i < D * C_OUT; i += 256) W[i] = w2[i];
    if (tid < C_OUT) bb[tid] = b2[tid];
    __syncthreads();

    int warp = tid >> 5, lane = tid & 31;
    int row = blockIdx.x * 8 + warp;
    const float* hr = g_bufB + (size_t)row * D;
    float a[4];
#pragma unroll
    for (int t = 0; t < 4; t++) a[t] = hr[lane + t * 32];

    float acc[C_OUT];
#pragma unroll
    for (int c = 0; c < C_OUT; c++) {
        float s = 0.0f;
#pragma unroll
        for (int t = 0; t < 4; t++) s = fmaf(a[t], W[(lane + t * 32) * C_OUT + c], s);
        acc[c] = s;
    }
#pragma unroll
    for (int off = 16; off; off >>= 1)
#pragma unroll
        for (int c = 0; c < C_OUT; c++) acc[c] += __shfl_xor_sync(0xffffffffu, acc[c], off);

    if (lane == 0) {
        float m = -1e30f;
#pragma unroll
        for (int c = 0; c < C_OUT; c++) { acc[c] += bb[c]; m = fmaxf(m, acc[c]); }
        float se = 0.0f;
#pragma unroll
        for (int c = 0; c < C_OUT; c++) se += expf(acc[c] - m);
        float lse = logf(se) + m;
        float4* o4 = (float4*)(out + (size_t)row * C_OUT);
        o4[0] = make_float4(acc[0] - lse, acc[1] - lse, acc[2] - lse, acc[3] - lse);
        o4[1] = make_float4(acc[4] - lse, acc[5] - lse, acc[6] - lse, acc[7] - lse);
    }
}

// ---------------- launch (kernel launches ONLY — graph-capture safe) -------
extern "C" void kernel_launch(void* const* d_in, const int* in_sizes, int n_in,
                              void* d_out, int out_size) {
    const float* x      = (const float*)d_in[0];
    const int*   ei     = (const int*)  d_in[1];
    const int*   sidx   = (const int*)  d_in[2];
    const int*   didx   = (const int*)  d_in[3];
    const float* emb_w  = (const float*)d_in[4];
    const float* emb_b  = (const float*)d_in[5];
    const float* gcn1_w = (const float*)d_in[6];
    const float* gcn1_b = (const float*)d_in[7];
    const float* gcn2_w = (const float*)d_in[8];
    const float* gcn2_b = (const float*)d_in[9];
    const float* bn_g   = (const float*)d_in[10];
    const float* bn_b   = (const float*)d_in[11];
    const float* ff_w   = (const float*)d_in[12];
    const float* ff_b   = (const float*)d_in[13];
    const float* ff1_w  = (const float*)d_in[14];
    const float* ff1_b  = (const float*)d_in[15];
    const float* ff2_w  = (const float*)d_in[16];
    const float* ff2_b  = (const float*)d_in[17];
    float* out = (float*)d_out;

    const int* src = ei;
    const int* dst = ei + E_EDGES;
    const int GM = N_NODES / 128;   // 512 gemm blocks

    // degree + norm (also zeroes BN accumulators); weight prep
    deg_init_kernel<<<N_NODES / 256, 256>>>();
    deg_count_kernel<<<E_EDGES / 256, 256>>>(dst);
    dinv_kernel<<<N_NODES / 256, 256>>>();
    prep_w_kernel<<<D + 1, D>>>(emb_w, emb_b, gcn1_w);
    prep_bfrag_kernel<<<64, 256>>>(gcn2_w, ff_w, ff1_w);

    // GCN1: t1 = x@(We W1) + (be W1) -> bufB ; dinv^2*t1 -> bufC
    tcgemm<0,1,true, 0,2,3,0,1><<<GM, 256>>>(x, nullptr, nullptr);
    scatter_edges_kernel<2, 3><<<E_EDGES / 8, 256>>>(src, dst);    // acc1 -> bufC

    // GCN2: A = relu(acc1 + b1), t2 -> bufB, dinv^2*t2 -> bufC
    tcgemm<1,0,true, 3,2,3,1,0><<<GM, 256>>>(nullptr, nullptr, gcn1_b);
    scatter_edges_kernel<2, 3><<<E_EDGES / 8, 256>>>(src, dst);    // acc2 -> bufC

    // per-graph bias (ff_b + b2@Wf + src/dest gathered terms)
    gbias_kernel<<<BATCH, D>>>(sidx, didx, ff_w, ff_b, gcn2_b);

    // ff: h3 = acc2 @ Wf[0:128] + gbias -> bufA
    tcgemm<0,3,false,3,1,3,2,0><<<GM, 256>>>(nullptr, nullptr, nullptr);
    bn_stats_kernel<1><<<N_NODES / 256, 256>>>();
    bn_fin_kernel<<<1, D>>>(bn_g, bn_b);

    // ff1: h5 = relu( bnrelu(h3) @ W1f + b1f ) -> bufB
    tcgemm<2,2,false,1,2,3,3,0><<<GM, 256>>>(nullptr, ff1_b, nullptr);

    // logits + log_softmax
    final_kernel<<<N_NODES / 8, 256>>>(ff2_w, ff2_b, out);
}

// round 9
// speedup vs baseline: 2.3347x; 1.4534x over previous
#include <cuda_runtime.h>
#include <cuda_bf16.h>
#include <cstdint>

#define N_NODES 65536
#define N_PER   2048
#define BATCH   32
#define E_EDGES 1048576
#define D       128
#define C_OUT   8

// ---------------- scratch (device globals: allocation-free) ----------------
__device__ float g_bufA[N_NODES * D];
__device__ float g_bufB[N_NODES * D];
__device__ float g_bufC[N_NODES * D];
__device__ float g_dinv[N_NODES];
__device__ float g_gbias[BATCH * D];
__device__ float g_sum[D];
__device__ float g_sumsq[D];
__device__ float g_scale[D];
__device__ float g_shift[D];
__device__ float g_wp[D * D];   // emb_w @ gcn1_w
__device__ float g_bp[D];       // emb_b @ gcn1_w
// pre-packed B fragments for mma.sync: [img][kt(8)][nt(16)][lane(32)] uint2
__device__ uint2 g_bfragH[4 * 8 * 16 * 32];
__device__ uint2 g_bfragL[4 * 8 * 16 * 32];
// CSR by destination
__device__ int g_cnt[N_NODES];
__device__ int g_ptr[N_NODES + 1];
__device__ int g_cursor[N_NODES];
__device__ int g_csr_src[E_EDGES];
__device__ int g_bsum[256];

__device__ __forceinline__ float* buf_ptr_dev(int sel) {
    switch (sel) {
        case 1: return g_bufA;
        case 2: return g_bufB;
        default: return g_bufC;
    }
}

// ---------------- helpers ----------------
__device__ __forceinline__ void mma_bf16(float c[4], uint32_t a0, uint32_t a1,
                                         uint32_t a2, uint32_t a3,
                                         uint32_t b0, uint32_t b1) {
    asm volatile(
        "mma.sync.aligned.m16n8k16.row.col.f32.bf16.bf16.f32 "
        "{%0,%1,%2,%3}, {%4,%5,%6,%7}, {%8,%9}, {%0,%1,%2,%3};"
        : "+f"(c[0]), "+f"(c[1]), "+f"(c[2]), "+f"(c[3])
        : "r"(a0), "r"(a1), "r"(a2), "r"(a3), "r"(b0), "r"(b1));
}
__device__ __forceinline__ uint32_t pack_bf16x2(float lo, float hi) {
    __nv_bfloat162 h = __floats2bfloat162_rn(lo, hi);
    return *(uint32_t*)&h;
}
__device__ __forceinline__ void split2(float v0, float v1, uint32_t& h, uint32_t& l) {
    __nv_bfloat16 h0 = __float2bfloat16(v0);
    __nv_bfloat16 h1 = __float2bfloat16(v1);
    float r0 = v0 - __bfloat162float(h0);
    float r1 = v1 - __bfloat162float(h1);
    __nv_bfloat162 hp; hp.x = h0; hp.y = h1;
    h = *(uint32_t*)&hp;
    l = pack_bf16x2(r0, r1);
}

// ---------------- degree / CSR build ----------------
__global__ void deg_init_kernel() {
    int i = blockIdx.x * 256 + threadIdx.x;
    if (i < N_NODES) g_cnt[i] = 0;
    if (i < D) { g_sum[i] = 0.0f; g_sumsq[i] = 0.0f; }
}
__global__ void deg_count_kernel(const int* __restrict__ dst) {
    int e = blockIdx.x * 256 + threadIdx.x;
    if (e < E_EDGES) atomicAdd(&g_cnt[dst[e]], 1);
}
__global__ void dinv_kernel() {
    int i = blockIdx.x * 256 + threadIdx.x;
    if (i < N_NODES) g_dinv[i] = rsqrtf((float)g_cnt[i] + 1.0f);  // +1 self-loop
}
// scan stage 1: per-block exclusive scan of g_cnt -> g_ptr, block totals -> g_bsum
__global__ void scan1_kernel() {
    __shared__ int sh[256];
    int t = threadIdx.x;
    int i = blockIdx.x * 256 + t;
    int v = g_cnt[i];
    sh[t] = v;
    __syncthreads();
#pragma unroll
    for (int off = 1; off < 256; off <<= 1) {
        int x = (t >= off) ? sh[t - off] : 0;
        __syncthreads();
        sh[t] += x;
        __syncthreads();
    }
    g_ptr[i] = sh[t] - v;                 // exclusive
    if (t == 255) g_bsum[blockIdx.x] = sh[t];
}
// scan stage 2: exclusive scan of the 256 block sums (single block)
__global__ void scan2_kernel() {
    __shared__ int sh[256];
    int t = threadIdx.x;
    int v = g_bsum[t];
    sh[t] = v;
    __syncthreads();
#pragma unroll
    for (int off = 1; off < 256; off <<= 1) {
        int x = (t >= off) ? sh[t - off] : 0;
        __syncthreads();
        sh[t] += x;
        __syncthreads();
    }
    g_bsum[t] = sh[t] - v;
}
// scan stage 3: add block offsets, init cursors
__global__ void scan3_kernel() {
    int i = blockIdx.x * 256 + threadIdx.x;
    int p = g_ptr[i] + g_bsum[blockIdx.x];
    g_ptr[i] = p;
    g_cursor[i] = p;
    if (i == 0) g_ptr[N_NODES] = E_EDGES;
}
__global__ void fill_kernel(const int* __restrict__ src, const int* __restrict__ dst) {
    int e = blockIdx.x * 256 + threadIdx.x;
    if (e < E_EDGES) {
        int pos = atomicAdd(&g_cursor[dst[e]], 1);
        g_csr_src[pos] = src[e];
    }
}

// ---------------- weight prefold (8 rows/block) ----------------
__global__ void prep_w_kernel(const float* __restrict__ emb_w,
                              const float* __restrict__ emb_b,
                              const float* __restrict__ gcn1_w) {
    __shared__ float arow[8][D];
    int c = threadIdx.x;          // 0..127
    int r0 = blockIdx.x * 8;      // 17 blocks cover 129 rows
#pragma unroll
    for (int j = 0; j < 8; j++) {
        int r = r0 + j;
        if (r < D)       arow[j][c] = emb_w[r * D + c];
        else if (r == D) arow[j][c] = emb_b[c];
    }
    __syncthreads();
    float acc[8];
#pragma unroll
    for (int j = 0; j < 8; j++) acc[j] = 0.0f;
    for (int k = 0; k < D; k++) {
        float w = gcn1_w[k * D + c];
#pragma unroll
        for (int j = 0; j < 8; j++) acc[j] = fmaf(arow[j][k], w, acc[j]);
    }
#pragma unroll
    for (int j = 0; j < 8; j++) {
        int r = r0 + j;
        if (r < D)       g_wp[r * D + c] = acc[j];
        else if (r == D) g_bp[c] = acc[j];
    }
}

// ---------------- B fragment prep ----------------
__global__ void prep_bfrag_kernel(const float* __restrict__ gcn2_w,
                                  const float* __restrict__ ff_w,
                                  const float* __restrict__ ff1_w) {
    int idx  = blockIdx.x * 256 + threadIdx.x;   // 0..16383
    int lane = idx & 31;
    int nt   = (idx >> 5) & 15;
    int kt   = (idx >> 9) & 7;
    int img  = idx >> 12;
    int g = lane >> 2, t = lane & 3;
    const float* W;
    if      (img == 0) W = g_wp;
    else if (img == 1) W = gcn2_w;
    else if (img == 2) W = ff_w;     // rows 0..127 only
    else               W = ff1_w;
    int n = nt * 8 + g;
    int k0 = kt * 16 + 2 * t;
    float w00 = W[(k0)     * D + n], w01 = W[(k0 + 1) * D + n];
    float w10 = W[(k0 + 8) * D + n], w11 = W[(k0 + 9) * D + n];
    uint32_t h0, l0, h1, l1;
    split2(w00, w01, h0, l0);
    split2(w10, w11, h1, l1);
    g_bfragH[idx] = make_uint2(h0, h1);
    g_bfragL[idx] = make_uint2(l0, l1);
}

// ---------------- mma.sync split-bf16 GEMM (same as R8, SCAT removed) ------
#define AS_STRIDE 68

template<int ATR, int EPI, int ASEL, int CSEL, int IMG, int BIASSEL>
__global__ __launch_bounds__(256) void tcgemm(const float* __restrict__ Aext,
                                              const float* __restrict__ biasext,
                                              const float* __restrict__ avec) {
    __shared__ __align__(16) __nv_bfloat16 AsH[128 * AS_STRIDE];
    __shared__ __align__(16) __nv_bfloat16 AsL[128 * AS_STRIDE];
    __shared__ float sbias[D];

    const float* A = (ASEL == 0) ? Aext : buf_ptr_dev(ASEL);
    const float* bias = (BIASSEL == 0) ? biasext : g_bp;
    float* Cm = buf_ptr_dev(CSEL);

    const int tid = threadIdx.x;
    const int wid = tid >> 5, lane = tid & 31;
    const int warpM = wid >> 1, warpN = wid & 1;
    const int g = lane >> 2, t = lane & 3;
    const int rowBase = blockIdx.x * 128;

    if (tid < D) {
        if (EPI == 1 || EPI == 2)      sbias[tid] = bias[tid];
        else if (EPI == 3)             sbias[tid] = g_gbias[(rowBase >> 11) * D + tid];
        else                           sbias[tid] = 0.0f;
    }

    float c[2][8][4];
#pragma unroll
    for (int m = 0; m < 2; m++)
#pragma unroll
        for (int n = 0; n < 8; n++)
#pragma unroll
            for (int q = 0; q < 4; q++) c[m][n][q] = 0.0f;

    for (int ch = 0; ch < 2; ch++) {
        __syncthreads();
#pragma unroll
        for (int i = 0; i < 8; i++) {
            int e = tid + i * 256;
            int row = e >> 4;
            int cp  = (e & 15) * 4;
            int col = ch * 64 + cp;
            float4 v = *(const float4*)(A + (size_t)(rowBase + row) * D + col);
            if (ATR == 1) {
                v.x = fmaxf(v.x + avec[col + 0], 0.0f);
                v.y = fmaxf(v.y + avec[col + 1], 0.0f);
                v.z = fmaxf(v.z + avec[col + 2], 0.0f);
                v.w = fmaxf(v.w + avec[col + 3], 0.0f);
            } else if (ATR == 2) {
                v.x = fmaxf(fmaf(v.x, g_scale[col + 0], g_shift[col + 0]), 0.0f);
                v.y = fmaxf(fmaf(v.y, g_scale[col + 1], g_shift[col + 1]), 0.0f);
                v.z = fmaxf(fmaf(v.z, g_scale[col + 2], g_shift[col + 2]), 0.0f);
                v.w = fmaxf(fmaf(v.w, g_scale[col + 3], g_shift[col + 3]), 0.0f);
            }
            uint32_t h0, l0, h1, l1;
            split2(v.x, v.y, h0, l0);
            split2(v.z, v.w, h1, l1);
            *(uint2*)&AsH[row * AS_STRIDE + cp] = make_uint2(h0, h1);
            *(uint2*)&AsL[row * AS_STRIDE + cp] = make_uint2(l0, l1);
        }
        __syncthreads();

#pragma unroll
        for (int kt = 0; kt < 4; kt++) {
            int ktg = ch * 4 + kt;
            uint32_t aH[2][4], aL[2][4];
#pragma unroll
            for (int m = 0; m < 2; m++) {
                int r0 = warpM * 32 + m * 16 + g;
                int r1 = r0 + 8;
                int cb = kt * 16 + 2 * t;
                aH[m][0] = *(const uint32_t*)&AsH[r0 * AS_STRIDE + cb];
                aH[m][1] = *(const uint32_t*)&AsH[r1 * AS_STRIDE + cb];
                aH[m][2] = *(const uint32_t*)&AsH[r0 * AS_STRIDE + cb + 8];
                aH[m][3] = *(const uint32_t*)&AsH[r1 * AS_STRIDE + cb + 8];
                aL[m][0] = *(const uint32_t*)&AsL[r0 * AS_STRIDE + cb];
                aL[m][1] = *(const uint32_t*)&AsL[r1 * AS_STRIDE + cb];
                aL[m][2] = *(const uint32_t*)&AsL[r0 * AS_STRIDE + cb + 8];
                aL[m][3] = *(const uint32_t*)&AsL[r1 * AS_STRIDE + cb + 8];
            }
            const uint2* bh = g_bfragH + ((size_t)(IMG * 8 + ktg) * 16 + warpN * 8) * 32 + lane;
            const uint2* bl = g_bfragL + ((size_t)(IMG * 8 + ktg) * 16 + warpN * 8) * 32 + lane;
#pragma unroll
            for (int nt = 0; nt < 8; nt++) {
                uint2 bH = bh[nt * 32];
                uint2 bL = bl[nt * 32];
#pragma unroll
                for (int m = 0; m < 2; m++) {
                    mma_bf16(c[m][nt], aH[m][0], aH[m][1], aH[m][2], aH[m][3], bH.x, bH.y);
                    mma_bf16(c[m][nt], aH[m][0], aH[m][1], aH[m][2], aH[m][3], bL.x, bL.y);
                    mma_bf16(c[m][nt], aL[m][0], aL[m][1], aL[m][2], aL[m][3], bH.x, bH.y);
                }
            }
        }
    }

#pragma unroll
    for (int m = 0; m < 2; m++) {
        int r0 = rowBase + warpM * 32 + m * 16 + g;
        int r1 = r0 + 8;
#pragma unroll
        for (int nt = 0; nt < 8; nt++) {
            int cn = warpN * 64 + nt * 8 + 2 * t;
            float v0 = c[m][nt][0], v1 = c[m][nt][1];
            float v2 = c[m][nt][2], v3 = c[m][nt][3];
            if (EPI >= 1) {
                float b0 = sbias[cn], b1 = sbias[cn + 1];
                v0 += b0; v1 += b1; v2 += b0; v3 += b1;
            }
            if (EPI == 2) {
                v0 = fmaxf(v0, 0.0f); v1 = fmaxf(v1, 0.0f);
                v2 = fmaxf(v2, 0.0f); v3 = fmaxf(v3, 0.0f);
            }
            *(float2*)(Cm + (size_t)r0 * D + cn) = make_float2(v0, v1);
            *(float2*)(Cm + (size_t)r1 * D + cn) = make_float2(v2, v3);
        }
    }
}

// ---------------- CSR gather: acc[d] = dinv_d^2 t[d] + dinv_d Σ dinv_s t[s] -
template<int TSEL, int OSEL>
__global__ __launch_bounds__(256) void gather_kernel() {
    const float* t = buf_ptr_dev(TSEL);
    float* acc = buf_ptr_dev(OSEL);
    int node = blockIdx.x * 8 + (threadIdx.x >> 5);
    int lane = threadIdx.x & 31;
    int p0 = g_ptr[node];
    int p1 = g_ptr[node + 1];
    float dd = g_dinv[node];
    float4 a = ((const float4*)(t + (size_t)node * D))[lane];
    float nn = dd * dd;
    a.x *= nn; a.y *= nn; a.z *= nn; a.w *= nn;
    for (int p = p0; p < p1; p++) {
        int s = g_csr_src[p];                 // broadcast across warp
        float ns = g_dinv[s] * dd;
        float4 v = ((const float4*)(t + (size_t)s * D))[lane];
        a.x = fmaf(v.x, ns, a.x);
        a.y = fmaf(v.y, ns, a.y);
        a.z = fmaf(v.z, ns, a.z);
        a.w = fmaf(v.w, ns, a.w);
    }
    ((float4*)(acc + (size_t)node * D))[lane] = a;
}

// ---------------- per-graph bias ----------------
__global__ void gbias_kernel(const int* __restrict__ sidx, const int* __restrict__ didx,
                             const float* __restrict__ ff_w, const float* __restrict__ ff_b,
                             const float* __restrict__ gcn2_b) {
    int b = blockIdx.x;
    int c = threadIdx.x;
    int srow = sidx[b] + b * N_PER;
    int drow = didx[b] + b * N_PER;
    const float* hs = g_bufC + (size_t)srow * D;
    const float* hd = g_bufC + (size_t)drow * D;
    float acc = ff_b[c];
    for (int k = 0; k < D; k++) {
        float b2 = gcn2_b[k];
        acc = fmaf(b2,         ff_w[k * D + c],           acc);
        acc = fmaf(hs[k] + b2, ff_w[(D + k) * D + c],     acc);
        acc = fmaf(hd[k] + b2, ff_w[(2 * D + k) * D + c], acc);
    }
    g_gbias[b * D + c] = acc;
}

// ---------------- batch-norm stats / finalize ----------------
template<int SEL>
__global__ void bn_stats_kernel() {
    const float* h = buf_ptr_dev(SEL);
    int col  = threadIdx.x & 127;
    int half = threadIdx.x >> 7;
    int rEnd = blockIdx.x * 256 + 256;
    float s = 0.0f, q = 0.0f;
    for (int r = blockIdx.x * 256 + half; r < rEnd; r += 2) {
        float v = h[(size_t)r * D + col];
        s += v;
        q = fmaf(v, v, q);
    }
    atomicAdd(&g_sum[col], s);
    atomicAdd(&g_sumsq[col], q);
}
__global__ void bn_fin_kernel(const float* __restrict__ gamma, const float* __restrict__ beta) {
    int c = threadIdx.x;
    float inv_n = 1.0f / (float)N_NODES;
    float mean = g_sum[c] * inv_n;
    float var  = g_sumsq[c] * inv_n - mean * mean;
    float rstd = rsqrtf(var + 1e-5f);
    float sc = gamma[c] * rstd;
    g_scale[c] = sc;
    g_shift[c] = beta[c] - mean * sc;
}

// ---------------- final: [N,128]@[128,8] + bias + log_softmax --------------
__global__ __launch_bounds__(256) void final_kernel(const float* __restrict__ w2,
                                                    const float* __restrict__ b2,
                                                    float* __restrict__ out) {
    __shared__ float W[D * C_OUT];
    __shared__ float bb[C_OUT];
    int tid = threadIdx.x;
    for (int i = tid; i < D * C_OUT; i += 256) W[i] = w2[i];
    if (tid < C_OUT) bb[tid] = b2[tid];
    __syncthreads();

    int warp = tid >> 5, lane = tid & 31;
    int row = blockIdx.x * 8 + warp;
    const float* hr = g_bufB + (size_t)row * D;
    float a[4];
#pragma unroll
    for (int t = 0; t < 4; t++) a[t] = hr[lane + t * 32];

    float acc[C_OUT];
#pragma unroll
    for (int c = 0; c < C_OUT; c++) {
        float s = 0.0f;
#pragma unroll
        for (int t = 0; t < 4; t++) s = fmaf(a[t], W[(lane + t * 32) * C_OUT + c], s);
        acc[c] = s;
    }
#pragma unroll
    for (int off = 16; off; off >>= 1)
#pragma unroll
        for (int c = 0; c < C_OUT; c++) acc[c] += __shfl_xor_sync(0xffffffffu, acc[c], off);

    if (lane == 0) {
        float m = -1e30f;
#pragma unroll
        for (int c = 0; c < C_OUT; c++) { acc[c] += bb[c]; m = fmaxf(m, acc[c]); }
        float se = 0.0f;
#pragma unroll
        for (int c = 0; c < C_OUT; c++) se += expf(acc[c] - m);
        float lse = logf(se) + m;
        float4* o4 = (float4*)(out + (size_t)row * C_OUT);
        o4[0] = make_float4(acc[0] - lse, acc[1] - lse, acc[2] - lse, acc[3] - lse);
        o4[1] = make_float4(acc[4] - lse, acc[5] - lse, acc[6] - lse, acc[7] - lse);
    }
}

// ---------------- launch (kernel launches ONLY — graph-capture safe) -------
extern "C" void kernel_launch(void* const* d_in, const int* in_sizes, int n_in,
                              void* d_out, int out_size) {
    const float* x      = (const float*)d_in[0];
    const int*   ei     = (const int*)  d_in[1];
    const int*   sidx   = (const int*)  d_in[2];
    const int*   didx   = (const int*)  d_in[3];
    const float* emb_w  = (const float*)d_in[4];
    const float* emb_b  = (const float*)d_in[5];
    const float* gcn1_w = (const float*)d_in[6];
    const float* gcn1_b = (const float*)d_in[7];
    const float* gcn2_w = (const float*)d_in[8];
    const float* gcn2_b = (const float*)d_in[9];
    const float* bn_g   = (const float*)d_in[10];
    const float* bn_b   = (const float*)d_in[11];
    const float* ff_w   = (const float*)d_in[12];
    const float* ff_b   = (const float*)d_in[13];
    const float* ff1_w  = (const float*)d_in[14];
    const float* ff1_b  = (const float*)d_in[15];
    const float* ff2_w  = (const float*)d_in[16];
    const float* ff2_b  = (const float*)d_in[17];
    float* out = (float*)d_out;

    const int* src = ei;
    const int* dst = ei + E_EDGES;
    const int GM = N_NODES / 128;   // 512 gemm blocks

    // degree + CSR build + weight prep
    deg_init_kernel<<<N_NODES / 256, 256>>>();
    deg_count_kernel<<<E_EDGES / 256, 256>>>(dst);
    dinv_kernel<<<N_NODES / 256, 256>>>();
    scan1_kernel<<<256, 256>>>();
    scan2_kernel<<<1, 256>>>();
    scan3_kernel<<<256, 256>>>();
    fill_kernel<<<E_EDGES / 256, 256>>>(src, dst);
    prep_w_kernel<<<17, 128>>>(emb_w, emb_b, gcn1_w);
    prep_bfrag_kernel<<<64, 256>>>(gcn2_w, ff_w, ff1_w);

    // GCN1: t1 = x@(We W1) + (be W1) -> bufB ; gather -> bufC
    tcgemm<0,1,0,2,0,1><<<GM, 256>>>(x, nullptr, nullptr);
    gather_kernel<2, 3><<<N_NODES / 8, 256>>>();

    // GCN2: A = relu(acc1 + b1) from bufC, t2 -> bufB ; gather -> bufC
    tcgemm<1,0,3,2,1,0><<<GM, 256>>>(nullptr, nullptr, gcn1_b);
    gather_kernel<2, 3><<<N_NODES / 8, 256>>>();

    // per-graph bias (ff_b + b2@Wf + src/dest gathered terms)
    gbias_kernel<<<BATCH, D>>>(sidx, didx, ff_w, ff_b, gcn2_b);

    // ff: h3 = acc2 @ Wf[0:128] + gbias -> bufA
    tcgemm<0,3,3,1,2,0><<<GM, 256>>>(nullptr, nullptr, nullptr);
    bn_stats_kernel<1><<<N_NODES / 256, 256>>>();
    bn_fin_kernel<<<1, D>>>(bn_g, bn_b);

    // ff1: h5 = relu( bnrelu(h3) @ W1f + b1f ) -> bufB
    tcgemm<2,2,1,2,3,0><<<GM, 256>>>(nullptr, ff1_b, nullptr);

    // logits + log_softmax
    final_kernel<<<N_NODES / 8, 256>>>(ff2_w, ff2_b, out);
}

// round 10
// speedup vs baseline: 2.3360x; 1.0006x over previous
#include <cuda_runtime.h>
#include <cuda_bf16.h>
#include <cstdint>

#define N_NODES 65536
#define N_PER   2048
#define BATCH   32
#define E_EDGES 1048576
#define D       128
#define C_OUT   8

// ---------------- scratch (device globals: allocation-free) ----------------
__device__ float g_bufA[N_NODES * D];
__device__ float g_bufB[N_NODES * D];
__device__ float g_bufC[N_NODES * D];
__device__ float g_dinv[N_NODES];
__device__ float g_gbias[BATCH * D];
__device__ float g_sum[D];
__device__ float g_sumsq[D];
__device__ float g_scale[D];
__device__ float g_shift[D];
__device__ float g_wp[D * D];   // emb_w @ gcn1_w
__device__ float g_bp[D];       // emb_b @ gcn1_w
// pre-packed B fragments for mma.sync: [img][kt(8)][nt(16)][lane(32)] uint2
__device__ uint2 g_bfragH[4 * 8 * 16 * 32];
__device__ uint2 g_bfragL[4 * 8 * 16 * 32];
// CSR by destination
__device__ int g_cnt[N_NODES];
__device__ int g_ptr[N_NODES + 1];
__device__ int g_cursor[N_NODES];
__device__ int g_csr_src[E_EDGES];
__device__ int g_bsum[256];

__device__ __forceinline__ float* buf_ptr_dev(int sel) {
    switch (sel) {
        case 1: return g_bufA;
        case 2: return g_bufB;
        default: return g_bufC;
    }
}

// ---------------- helpers ----------------
__device__ __forceinline__ void mma_bf16(float c[4], uint32_t a0, uint32_t a1,
                                         uint32_t a2, uint32_t a3,
                                         uint32_t b0, uint32_t b1) {
    asm volatile(
        "mma.sync.aligned.m16n8k16.row.col.f32.bf16.bf16.f32 "
        "{%0,%1,%2,%3}, {%4,%5,%6,%7}, {%8,%9}, {%0,%1,%2,%3};"
        : "+f"(c[0]), "+f"(c[1]), "+f"(c[2]), "+f"(c[3])
        : "r"(a0), "r"(a1), "r"(a2), "r"(a3), "r"(b0), "r"(b1));
}
__device__ __forceinline__ uint32_t pack_bf16x2(float lo, float hi) {
    __nv_bfloat162 h = __floats2bfloat162_rn(lo, hi);
    return *(uint32_t*)&h;
}
__device__ __forceinline__ void split2(float v0, float v1, uint32_t& h, uint32_t& l) {
    __nv_bfloat16 h0 = __float2bfloat16(v0);
    __nv_bfloat16 h1 = __float2bfloat16(v1);
    float r0 = v0 - __bfloat162float(h0);
    float r1 = v1 - __bfloat162float(h1);
    __nv_bfloat162 hp; hp.x = h0; hp.y = h1;
    h = *(uint32_t*)&hp;
    l = pack_bf16x2(r0, r1);
}

// ---------------- degree / CSR build ----------------
__global__ void deg_init_kernel() {
    int i = blockIdx.x * 256 + threadIdx.x;
    if (i < N_NODES) g_cnt[i] = 0;
    if (i < D) { g_sum[i] = 0.0f; g_sumsq[i] = 0.0f; }
}
__global__ void deg_count_kernel(const int* __restrict__ dst) {
    int e = blockIdx.x * 256 + threadIdx.x;
    if (e < E_EDGES) atomicAdd(&g_cnt[dst[e]], 1);
}
__global__ void dinv_kernel() {
    int i = blockIdx.x * 256 + threadIdx.x;
    if (i < N_NODES) g_dinv[i] = rsqrtf((float)g_cnt[i] + 1.0f);  // +1 self-loop
}
// scan stage 1: per-block exclusive scan of g_cnt -> g_ptr, block totals -> g_bsum
__global__ void scan1_kernel() {
    __shared__ int sh[256];
    int t = threadIdx.x;
    int i = blockIdx.x * 256 + t;
    int v = g_cnt[i];
    sh[t] = v;
    __syncthreads();
#pragma unroll
    for (int off = 1; off < 256; off <<= 1) {
        int x = (t >= off) ? sh[t - off] : 0;
        __syncthreads();
        sh[t] += x;
        __syncthreads();
    }
    g_ptr[i] = sh[t] - v;                 // exclusive
    if (t == 255) g_bsum[blockIdx.x] = sh[t];
}
// scan stage 2: exclusive scan of the 256 block sums (single block)
__global__ void scan2_kernel() {
    __shared__ int sh[256];
    int t = threadIdx.x;
    int v = g_bsum[t];
    sh[t] = v;
    __syncthreads();
#pragma unroll
    for (int off = 1; off < 256; off <<= 1) {
        int x = (t >= off) ? sh[t - off] : 0;
        __syncthreads();
        sh[t] += x;
        __syncthreads();
    }
    g_bsum[t] = sh[t] - v;
}
// scan stage 3: add block offsets, init cursors
__global__ void scan3_kernel() {
    int i = blockIdx.x * 256 + threadIdx.x;
    int p = g_ptr[i] + g_bsum[blockIdx.x];
    g_ptr[i] = p;
    g_cursor[i] = p;
    if (i == 0) g_ptr[N_NODES] = E_EDGES;
}
__global__ void fill_kernel(const int* __restrict__ src, const int* __restrict__ dst) {
    int e = blockIdx.x * 256 + threadIdx.x;
    if (e < E_EDGES) {
        int pos = atomicAdd(&g_cursor[dst[e]], 1);
        g_csr_src[pos] = src[e];
    }
}

// ---------------- weight prefold (8 rows/block) ----------------
__global__ void prep_w_kernel(const float* __restrict__ emb_w,
                              const float* __restrict__ emb_b,
                              const float* __restrict__ gcn1_w) {
    __shared__ float arow[8][D];
    int c = threadIdx.x;          // 0..127
    int r0 = blockIdx.x * 8;      // 17 blocks cover 129 rows
#pragma unroll
    for (int j = 0; j < 8; j++) {
        int r = r0 + j;
        if (r < D)       arow[j][c] = emb_w[r * D + c];
        else if (r == D) arow[j][c] = emb_b[c];
    }
    __syncthreads();
    float acc[8];
#pragma unroll
    for (int j = 0; j < 8; j++) acc[j] = 0.0f;
    for (int k = 0; k < D; k++) {
        float w = gcn1_w[k * D + c];
#pragma unroll
        for (int j = 0; j < 8; j++) acc[j] = fmaf(arow[j][k], w, acc[j]);
    }
#pragma unroll
    for (int j = 0; j < 8; j++) {
        int r = r0 + j;
        if (r < D)       g_wp[r * D + c] = acc[j];
        else if (r == D) g_bp[c] = acc[j];
    }
}

// ---------------- B fragment prep ----------------
__global__ void prep_bfrag_kernel(const float* __restrict__ gcn2_w,
                                  const float* __restrict__ ff_w,
                                  const float* __restrict__ ff1_w) {
    int idx  = blockIdx.x * 256 + threadIdx.x;   // 0..16383
    int lane = idx & 31;
    int nt   = (idx >> 5) & 15;
    int kt   = (idx >> 9) & 7;
    int img  = idx >> 12;
    int g = lane >> 2, t = lane & 3;
    const float* W;
    if      (img == 0) W = g_wp;
    else if (img == 1) W = gcn2_w;
    else if (img == 2) W = ff_w;     // rows 0..127 only
    else               W = ff1_w;
    int n = nt * 8 + g;
    int k0 = kt * 16 + 2 * t;
    float w00 = W[(k0)     * D + n], w01 = W[(k0 + 1) * D + n];
    float w10 = W[(k0 + 8) * D + n], w11 = W[(k0 + 9) * D + n];
    uint32_t h0, l0, h1, l1;
    split2(w00, w01, h0, l0);
    split2(w10, w11, h1, l1);
    g_bfragH[idx] = make_uint2(h0, h1);
    g_bfragL[idx] = make_uint2(l0, l1);
}

// ---------------- mma.sync split-bf16 GEMM (same as R8, SCAT removed) ------
#define AS_STRIDE 68

template<int ATR, int EPI, int ASEL, int CSEL, int IMG, int BIASSEL>
__global__ __launch_bounds__(256) void tcgemm(const float* __restrict__ Aext,
                                              const float* __restrict__ biasext,
                                              const float* __restrict__ avec) {
    __shared__ __align__(16) __nv_bfloat16 AsH[128 * AS_STRIDE];
    __shared__ __align__(16) __nv_bfloat16 AsL[128 * AS_STRIDE];
    __shared__ float sbias[D];

    const float* A = (ASEL == 0) ? Aext : buf_ptr_dev(ASEL);
    const float* bias = (BIASSEL == 0) ? biasext : g_bp;
    float* Cm = buf_ptr_dev(CSEL);

    const int tid = threadIdx.x;
    const int wid = tid >> 5, lane = tid & 31;
    const int warpM = wid >> 1, warpN = wid & 1;
    const int g = lane >> 2, t = lane & 3;
    const int rowBase = blockIdx.x * 128;

    if (tid < D) {
        if (EPI == 1 || EPI == 2)      sbias[tid] = bias[tid];
        else if (EPI == 3)             sbias[tid] = g_gbias[(rowBase >> 11) * D + tid];
        else                           sbias[tid] = 0.0f;
    }

    float c[2][8][4];
#pragma unroll
    for (int m = 0; m < 2; m++)
#pragma unroll
        for (int n = 0; n < 8; n++)
#pragma unroll
            for (int q = 0; q < 4; q++) c[m][n][q] = 0.0f;

    for (int ch = 0; ch < 2; ch++) {
        __syncthreads();
#pragma unroll
        for (int i = 0; i < 8; i++) {
            int e = tid + i * 256;
            int row = e >> 4;
            int cp  = (e & 15) * 4;
            int col = ch * 64 + cp;
            float4 v = *(const float4*)(A + (size_t)(rowBase + row) * D + col);
            if (ATR == 1) {
                v.x = fmaxf(v.x + avec[col + 0], 0.0f);
                v.y = fmaxf(v.y + avec[col + 1], 0.0f);
                v.z = fmaxf(v.z + avec[col + 2], 0.0f);
                v.w = fmaxf(v.w + avec[col + 3], 0.0f);
            } else if (ATR == 2) {
                v.x = fmaxf(fmaf(v.x, g_scale[col + 0], g_shift[col + 0]), 0.0f);
                v.y = fmaxf(fmaf(v.y, g_scale[col + 1], g_shift[col + 1]), 0.0f);
                v.z = fmaxf(fmaf(v.z, g_scale[col + 2], g_shift[col + 2]), 0.0f);
                v.w = fmaxf(fmaf(v.w, g_scale[col + 3], g_shift[col + 3]), 0.0f);
            }
            uint32_t h0, l0, h1, l1;
            split2(v.x, v.y, h0, l0);
            split2(v.z, v.w, h1, l1);
            *(uint2*)&AsH[row * AS_STRIDE + cp] = make_uint2(h0, h1);
            *(uint2*)&AsL[row * AS_STRIDE + cp] = make_uint2(l0, l1);
        }
        __syncthreads();

#pragma unroll
        for (int kt = 0; kt < 4; kt++) {
            int ktg = ch * 4 + kt;
            uint32_t aH[2][4], aL[2][4];
#pragma unroll
            for (int m = 0; m < 2; m++) {
                int r0 = warpM * 32 + m * 16 + g;
                int r1 = r0 + 8;
                int cb = kt * 16 + 2 * t;
                aH[m][0] = *(const uint32_t*)&AsH[r0 * AS_STRIDE + cb];
                aH[m][1] = *(const uint32_t*)&AsH[r1 * AS_STRIDE + cb];
                aH[m][2] = *(const uint32_t*)&AsH[r0 * AS_STRIDE + cb + 8];
                aH[m][3] = *(const uint32_t*)&AsH[r1 * AS_STRIDE + cb + 8];
                aL[m][0] = *(const uint32_t*)&AsL[r0 * AS_STRIDE + cb];
                aL[m][1] = *(const uint32_t*)&AsL[r1 * AS_STRIDE + cb];
                aL[m][2] = *(const uint32_t*)&AsL[r0 * AS_STRIDE + cb + 8];
                aL[m][3] = *(const uint32_t*)&AsL[r1 * AS_STRIDE + cb + 8];
            }
            const uint2* bh = g_bfragH + ((size_t)(IMG * 8 + ktg) * 16 + warpN * 8) * 32 + lane;
            const uint2* bl = g_bfragL + ((size_t)(IMG * 8 + ktg) * 16 + warpN * 8) * 32 + lane;
#pragma unroll
            for (int nt = 0; nt < 8; nt++) {
                uint2 bH = bh[nt * 32];
                uint2 bL = bl[nt * 32];
#pragma unroll
                for (int m = 0; m < 2; m++) {
                    mma_bf16(c[m][nt], aH[m][0], aH[m][1], aH[m][2], aH[m][3], bH.x, bH.y);
                    mma_bf16(c[m][nt], aH[m][0], aH[m][1], aH[m][2], aH[m][3], bL.x, bL.y);
                    mma_bf16(c[m][nt], aL[m][0], aL[m][1], aL[m][2], aL[m][3], bH.x, bH.y);
                }
            }
        }
    }

#pragma unroll
    for (int m = 0; m < 2; m++) {
        int r0 = rowBase + warpM * 32 + m * 16 + g;
        int r1 = r0 + 8;
#pragma unroll
        for (int nt = 0; nt < 8; nt++) {
            int cn = warpN * 64 + nt * 8 + 2 * t;
            float v0 = c[m][nt][0], v1 = c[m][nt][1];
            float v2 = c[m][nt][2], v3 = c[m][nt][3];
            if (EPI >= 1) {
                float b0 = sbias[cn], b1 = sbias[cn + 1];
                v0 += b0; v1 += b1; v2 += b0; v3 += b1;
            }
            if (EPI == 2) {
                v0 = fmaxf(v0, 0.0f); v1 = fmaxf(v1, 0.0f);
                v2 = fmaxf(v2, 0.0f); v3 = fmaxf(v3, 0.0f);
            }
            *(float2*)(Cm + (size_t)r0 * D + cn) = make_float2(v0, v1);
            *(float2*)(Cm + (size_t)r1 * D + cn) = make_float2(v2, v3);
        }
    }
}

// ---------------- CSR gather: acc[d] = dinv_d^2 t[d] + dinv_d Σ dinv_s t[s] -
template<int TSEL, int OSEL>
__global__ __launch_bounds__(256) void gather_kernel() {
    const float* t = buf_ptr_dev(TSEL);
    float* acc = buf_ptr_dev(OSEL);
    int node = blockIdx.x * 8 + (threadIdx.x >> 5);
    int lane = threadIdx.x & 31;
    int p0 = g_ptr[node];
    int p1 = g_ptr[node + 1];
    float dd = g_dinv[node];
    float4 a = ((const float4*)(t + (size_t)node * D))[lane];
    float nn = dd * dd;
    a.x *= nn; a.y *= nn; a.z *= nn; a.w *= nn;
    for (int p = p0; p < p1; p++) {
        int s = g_csr_src[p];                 // broadcast across warp
        float ns = g_dinv[s] * dd;
        float4 v = ((const float4*)(t + (size_t)s * D))[lane];
        a.x = fmaf(v.x, ns, a.x);
        a.y = fmaf(v.y, ns, a.y);
        a.z = fmaf(v.z, ns, a.z);
        a.w = fmaf(v.w, ns, a.w);
    }
    ((float4*)(acc + (size_t)node * D))[lane] = a;
}

// ---------------- per-graph bias ----------------
__global__ void gbias_kernel(const int* __restrict__ sidx, const int* __restrict__ didx,
                             const float* __restrict__ ff_w, const float* __restrict__ ff_b,
                             const float* __restrict__ gcn2_b) {
    int b = blockIdx.x;
    int c = threadIdx.x;
    int srow = sidx[b] + b * N_PER;
    int drow = didx[b] + b * N_PER;
    const float* hs = g_bufC + (size_t)srow * D;
    const float* hd = g_bufC + (size_t)drow * D;
    float acc = ff_b[c];
    for (int k = 0; k < D; k++) {
        float b2 = gcn2_b[k];
        acc = fmaf(b2,         ff_w[k * D + c],           acc);
        acc = fmaf(hs[k] + b2, ff_w[(D + k) * D + c],     acc);
        acc = fmaf(hd[k] + b2, ff_w[(2 * D + k) * D + c], acc);
    }
    g_gbias[b * D + c] = acc;
}

// ---------------- batch-norm stats / finalize ----------------
template<int SEL>
__global__ void bn_stats_kernel() {
    const float* h = buf_ptr_dev(SEL);
    int col  = threadIdx.x & 127;
    int half = threadIdx.x >> 7;
    int rEnd = blockIdx.x * 256 + 256;
    float s = 0.0f, q = 0.0f;
    for (int r = blockIdx.x * 256 + half; r < rEnd; r += 2) {
        float v = h[(size_t)r * D + col];
        s += v;
        q = fmaf(v, v, q);
    }
    atomicAdd(&g_sum[col], s);
    atomicAdd(&g_sumsq[col], q);
}
__global__ void bn_fin_kernel(const float* __restrict__ gamma, const float* __restrict__ beta) {
    int c = threadIdx.x;
    float inv_n = 1.0f / (float)N_NODES;
    float mean = g_sum[c] * inv_n;
    float var  = g_sumsq[c] * inv_n - mean * mean;
    float rstd = rsqrtf(var + 1e-5f);
    float sc = gamma[c] * rstd;
    g_scale[c] = sc;
    g_shift[c] = beta[c] - mean * sc;
}

// ---------------- final: [N,128]@[128,8] + bias + log_softmax --------------
__global__ __launch_bounds__(256) void final_kernel(const float* __restrict__ w2,
                                                    const float* __restrict__ b2,
                                                    float* __restrict__ out) {
    __shared__ float W[D * C_OUT];
    __shared__ float bb[C_OUT];
    int tid = threadIdx.x;
    for (int i = tid; i < D * C_OUT; i += 256) W[i] = w2[i];
    if (tid < C_OUT) bb[tid] = b2[tid];
    __syncthreads();

    int warp = tid >> 5, lane = tid & 31;
    int row = blockIdx.x * 8 + warp;
    const float* hr = g_bufB + (size_t)row * D;
    float a[4];
#pragma unroll
    for (int t = 0; t < 4; t++) a[t] = hr[lane + t * 32];

    float acc[C_OUT];
#pragma unroll
    for (int c = 0; c < C_OUT; c++) {
        float s = 0.0f;
#pragma unroll
        for (int t = 0; t < 4; t++) s = fmaf(a[t], W[(lane + t * 32) * C_OUT + c], s);
        acc[c] = s;
    }
#pragma unroll
    for (int off = 16; off; off >>= 1)
#pragma unroll
        for (int c = 0; c < C_OUT; c++) acc[c] += __shfl_xor_sync(0xffffffffu, acc[c], off);

    if (lane == 0) {
        float m = -1e30f;
#pragma unroll
        for (int c = 0; c < C_OUT; c++) { acc[c] += bb[c]; m = fmaxf(m, acc[c]); }
        float se = 0.0f;
#pragma unroll
        for (int c = 0; c < C_OUT; c++) se += expf(acc[c] - m);
        float lse = logf(se) + m;
        float4* o4 = (float4*)(out + (size_t)row * C_OUT);
        o4[0] = make_float4(acc[0] - lse, acc[1] - lse, acc[2] - lse, acc[3] - lse);
        o4[1] = make_float4(acc[4] - lse, acc[5] - lse, acc[6] - lse, acc[7] - lse);
    }
}

// ---------------- launch (kernel launches ONLY — graph-capture safe) -------
extern "C" void kernel_launch(void* const* d_in, const int* in_sizes, int n_in,
                              void* d_out, int out_size) {
    const float* x      = (const float*)d_in[0];
    const int*   ei     = (const int*)  d_in[1];
    const int*   sidx   = (const int*)  d_in[2];
    const int*   didx   = (const int*)  d_in[3];
    const float* emb_w  = (const float*)d_in[4];
    const float* emb_b  = (const float*)d_in[5];
    const float* gcn1_w = (const float*)d_in[6];
    const float* gcn1_b = (const float*)d_in[7];
    const float* gcn2_w = (const float*)d_in[8];
    const float* gcn2_b = (const float*)d_in[9];
    const float* bn_g   = (const float*)d_in[10];
    const float* bn_b   = (const float*)d_in[11];
    const float* ff_w   = (const float*)d_in[12];
    const float* ff_b   = (const float*)d_in[13];
    const float* ff1_w  = (const float*)d_in[14];
    const float* ff1_b  = (const float*)d_in[15];
    const float* ff2_w  = (const float*)d_in[16];
    const float* ff2_b  = (const float*)d_in[17];
    float* out = (float*)d_out;

    const int* src = ei;
    const int* dst = ei + E_EDGES;
    const int GM = N_NODES / 128;   // 512 gemm blocks

    // degree + CSR build + weight prep
    deg_init_kernel<<<N_NODES / 256, 256>>>();
    deg_count_kernel<<<E_EDGES / 256, 256>>>(dst);
    dinv_kernel<<<N_NODES / 256, 256>>>();
    scan1_kernel<<<256, 256>>>();
    scan2_kernel<<<1, 256>>>();
    scan3_kernel<<<256, 256>>>();
    fill_kernel<<<E_EDGES / 256, 256>>>(src, dst);
    prep_w_kernel<<<17, 128>>>(emb_w, emb_b, gcn1_w);
    prep_bfrag_kernel<<<64, 256>>>(gcn2_w, ff_w, ff1_w);

    // GCN1: t1 = x@(We W1) + (be W1) -> bufB ; gather -> bufC
    tcgemm<0,1,0,2,0,1><<<GM, 256>>>(x, nullptr, nullptr);
    gather_kernel<2, 3><<<N_NODES / 8, 256>>>();

    // GCN2: A = relu(acc1 + b1) from bufC, t2 -> bufB ; gather -> bufC
    tcgemm<1,0,3,2,1,0><<<GM, 256>>>(nullptr, nullptr, gcn1_b);
    gather_kernel<2, 3><<<N_NODES / 8, 256>>>();

    // per-graph bias (ff_b + b2@Wf + src/dest gathered terms)
    gbias_kernel<<<BATCH, D>>>(sidx, didx, ff_w, ff_b, gcn2_b);

    // ff: h3 = acc2 @ Wf[0:128] + gbias -> bufA
    tcgemm<0,3,3,1,2,0><<<GM, 256>>>(nullptr, nullptr, nullptr);
    bn_stats_kernel<1><<<N_NODES / 256, 256>>>();
    bn_fin_kernel<<<1, D>>>(bn_g, bn_b);

    // ff1: h5 = relu( bnrelu(h3) @ W1f + b1f ) -> bufB
    tcgemm<2,2,1,2,3,0><<<GM, 256>>>(nullptr, ff1_b, nullptr);

    // logits + log_softmax
    final_kernel<<<N_NODES / 8, 256>>>(ff2_w, ff2_b, out);
}

// round 11
// speedup vs baseline: 2.4850x; 1.0638x over previous
#include <cuda_runtime.h>
#include <cuda_bf16.h>
#include <cstdint>

#define N_NODES 65536
#define N_PER   2048
#define BATCH   32
#define E_EDGES 1048576
#define D       128
#define C_OUT   8

// ---------------- scratch (device globals: allocation-free) ----------------
__device__ float g_bufA[N_NODES * D];
__device__ float g_bufB[N_NODES * D];
__device__ float g_bufC[N_NODES * D];
__device__ float g_dinv[N_NODES];
__device__ float g_gbias[BATCH * D];
__device__ float g_sum[D];
__device__ float g_sumsq[D];
__device__ float g_scale[D];
__device__ float g_shift[D];
__device__ float g_wp[D * D];   // emb_w @ gcn1_w
__device__ float g_bp[D];       // emb_b @ gcn1_w
// pre-packed B fragments for mma.sync: [img][kt(8)][nt(16)][lane(32)] uint2
__device__ uint2 g_bfragH[4 * 8 * 16 * 32];
__device__ uint2 g_bfragL[4 * 8 * 16 * 32];
// CSR by destination
__device__ int g_cnt[N_NODES];
__device__ int g_ptr[N_NODES + 1];
__device__ int g_cursor[N_NODES];
__device__ int g_csr_src[E_EDGES];
__device__ int g_bsum[256];

__device__ __forceinline__ float* buf_ptr_dev(int sel) {
    switch (sel) {
        case 1: return g_bufA;
        case 2: return g_bufB;
        default: return g_bufC;
    }
}

// ---------------- helpers ----------------
__device__ __forceinline__ void mma_bf16(float c[4], uint32_t a0, uint32_t a1,
                                         uint32_t a2, uint32_t a3,
                                         uint32_t b0, uint32_t b1) {
    asm volatile(
        "mma.sync.aligned.m16n8k16.row.col.f32.bf16.bf16.f32 "
        "{%0,%1,%2,%3}, {%4,%5,%6,%7}, {%8,%9}, {%0,%1,%2,%3};"
        : "+f"(c[0]), "+f"(c[1]), "+f"(c[2]), "+f"(c[3])
        : "r"(a0), "r"(a1), "r"(a2), "r"(a3), "r"(b0), "r"(b1));
}
__device__ __forceinline__ uint32_t pack_bf16x2(float lo, float hi) {
    __nv_bfloat162 h = __floats2bfloat162_rn(lo, hi);
    return *(uint32_t*)&h;
}
__device__ __forceinline__ void split2(float v0, float v1, uint32_t& h, uint32_t& l) {
    __nv_bfloat16 h0 = __float2bfloat16(v0);
    __nv_bfloat16 h1 = __float2bfloat16(v1);
    float r0 = v0 - __bfloat162float(h0);
    float r1 = v1 - __bfloat162float(h1);
    __nv_bfloat162 hp; hp.x = h0; hp.y = h1;
    h = *(uint32_t*)&hp;
    l = pack_bf16x2(r0, r1);
}

// ---------------- degree / CSR build ----------------
__global__ void deg_init_kernel() {
    int i = blockIdx.x * 256 + threadIdx.x;
    if (i < N_NODES) g_cnt[i] = 0;
    if (i < D) { g_sum[i] = 0.0f; g_sumsq[i] = 0.0f; }
}
__global__ void deg_count_kernel(const int* __restrict__ dst) {
    int e = blockIdx.x * 256 + threadIdx.x;
    if (e < E_EDGES) atomicAdd(&g_cnt[dst[e]], 1);
}
// scan stage 1: per-block exclusive scan of g_cnt -> g_ptr (+ dinv fused)
__global__ void scan1_kernel() {
    __shared__ int sh[256];
    int t = threadIdx.x;
    int i = blockIdx.x * 256 + t;
    int v = g_cnt[i];
    g_dinv[i] = rsqrtf((float)v + 1.0f);  // +1 self-loop (fused dinv)
    sh[t] = v;
    __syncthreads();
#pragma unroll
    for (int off = 1; off < 256; off <<= 1) {
        int x = (t >= off) ? sh[t - off] : 0;
        __syncthreads();
        sh[t] += x;
        __syncthreads();
    }
    g_ptr[i] = sh[t] - v;                 // exclusive
    if (t == 255) g_bsum[blockIdx.x] = sh[t];
}
__global__ void scan2_kernel() {
    __shared__ int sh[256];
    int t = threadIdx.x;
    int v = g_bsum[t];
    sh[t] = v;
    __syncthreads();
#pragma unroll
    for (int off = 1; off < 256; off <<= 1) {
        int x = (t >= off) ? sh[t - off] : 0;
        __syncthreads();
        sh[t] += x;
        __syncthreads();
    }
    g_bsum[t] = sh[t] - v;
}
__global__ void scan3_kernel() {
    int i = blockIdx.x * 256 + threadIdx.x;
    int p = g_ptr[i] + g_bsum[blockIdx.x];
    g_ptr[i] = p;
    g_cursor[i] = p;
    if (i == 0) g_ptr[N_NODES] = E_EDGES;
}
__global__ void fill_kernel(const int* __restrict__ src, const int* __restrict__ dst) {
    int e = blockIdx.x * 256 + threadIdx.x;
    if (e < E_EDGES) {
        int pos = atomicAdd(&g_cursor[dst[e]], 1);
        g_csr_src[pos] = src[e];
    }
}

// ---------------- weight prefold (8 rows/block) ----------------
__global__ void prep_w_kernel(const float* __restrict__ emb_w,
                              const float* __restrict__ emb_b,
                              const float* __restrict__ gcn1_w) {
    __shared__ float arow[8][D];
    int c = threadIdx.x;
    int r0 = blockIdx.x * 8;
#pragma unroll
    for (int j = 0; j < 8; j++) {
        int r = r0 + j;
        if (r < D)       arow[j][c] = emb_w[r * D + c];
        else if (r == D) arow[j][c] = emb_b[c];
    }
    __syncthreads();
    float acc[8];
#pragma unroll
    for (int j = 0; j < 8; j++) acc[j] = 0.0f;
    for (int k = 0; k < D; k++) {
        float w = gcn1_w[k * D + c];
#pragma unroll
        for (int j = 0; j < 8; j++) acc[j] = fmaf(arow[j][k], w, acc[j]);
    }
#pragma unroll
    for (int j = 0; j < 8; j++) {
        int r = r0 + j;
        if (r < D)       g_wp[r * D + c] = acc[j];
        else if (r == D) g_bp[c] = acc[j];
    }
}

// ---------------- B fragment prep ----------------
__global__ void prep_bfrag_kernel(const float* __restrict__ gcn2_w,
                                  const float* __restrict__ ff_w,
                                  const float* __restrict__ ff1_w) {
    int idx  = blockIdx.x * 256 + threadIdx.x;
    int lane = idx & 31;
    int nt   = (idx >> 5) & 15;
    int kt   = (idx >> 9) & 7;
    int img  = idx >> 12;
    int g = lane >> 2, t = lane & 3;
    const float* W;
    if      (img == 0) W = g_wp;
    else if (img == 1) W = gcn2_w;
    else if (img == 2) W = ff_w;
    else               W = ff1_w;
    int n = nt * 8 + g;
    int k0 = kt * 16 + 2 * t;
    float w00 = W[(k0)     * D + n], w01 = W[(k0 + 1) * D + n];
    float w10 = W[(k0 + 8) * D + n], w11 = W[(k0 + 9) * D + n];
    uint32_t h0, l0, h1, l1;
    split2(w00, w01, h0, l0);
    split2(w10, w11, h1, l1);
    g_bfragH[idx] = make_uint2(h0, h1);
    g_bfragL[idx] = make_uint2(l0, l1);
}

// ---------------- mma.sync split-bf16 GEMM (+opt fused final) --------------
// ATR: 0 none, 1 relu(a+avec[k]), 2 relu(a*g_scale+g_shift)
// EPI: 0 none, 1 +bias, 2 relu(+bias), 3 +g_gbias[graph]
// FINAL: fold [128,8] logits GEMM + log_softmax, write to pout
#define AS_STRIDE 68

template<int ATR, int EPI, int ASEL, int CSEL, int IMG, int BIASSEL, int FINAL>
__global__ __launch_bounds__(256) void tcgemm(const float* __restrict__ Aext,
                                              const float* __restrict__ biasext,
                                              const float* __restrict__ avec,
                                              const float* __restrict__ w2,
                                              const float* __restrict__ b2,
                                              float* __restrict__ pout) {
    __shared__ __align__(16) __nv_bfloat16 AsH[128 * AS_STRIDE];
    __shared__ __align__(16) __nv_bfloat16 AsL[128 * AS_STRIDE];
    __shared__ float sbias[D];

    const float* A = (ASEL == 0) ? Aext : buf_ptr_dev(ASEL);
    const float* bias = (BIASSEL == 0) ? biasext : g_bp;
    float* Cm = buf_ptr_dev(CSEL);

    const int tid = threadIdx.x;
    const int wid = tid >> 5, lane = tid & 31;
    const int warpM = wid >> 1, warpN = wid & 1;
    const int g = lane >> 2, t = lane & 3;
    const int rowBase = blockIdx.x * 128;

    if (tid < D) {
        if (EPI == 1 || EPI == 2)      sbias[tid] = bias[tid];
        else if (EPI == 3)             sbias[tid] = g_gbias[(rowBase >> 11) * D + tid];
        else                           sbias[tid] = 0.0f;
    }

    float c[2][8][4];
#pragma unroll
    for (int m = 0; m < 2; m++)
#pragma unroll
        for (int n = 0; n < 8; n++)
#pragma unroll
            for (int q = 0; q < 4; q++) c[m][n][q] = 0.0f;

    for (int ch = 0; ch < 2; ch++) {
        __syncthreads();
#pragma unroll
        for (int i = 0; i < 8; i++) {
            int e = tid + i * 256;
            int row = e >> 4;
            int cp  = (e & 15) * 4;
            int col = ch * 64 + cp;
            float4 v = *(const float4*)(A + (size_t)(rowBase + row) * D + col);
            if (ATR == 1) {
                v.x = fmaxf(v.x + avec[col + 0], 0.0f);
                v.y = fmaxf(v.y + avec[col + 1], 0.0f);
                v.z = fmaxf(v.z + avec[col + 2], 0.0f);
                v.w = fmaxf(v.w + avec[col + 3], 0.0f);
            } else if (ATR == 2) {
                v.x = fmaxf(fmaf(v.x, g_scale[col + 0], g_shift[col + 0]), 0.0f);
                v.y = fmaxf(fmaf(v.y, g_scale[col + 1], g_shift[col + 1]), 0.0f);
                v.z = fmaxf(fmaf(v.z, g_scale[col + 2], g_shift[col + 2]), 0.0f);
                v.w = fmaxf(fmaf(v.w, g_scale[col + 3], g_shift[col + 3]), 0.0f);
            }
            uint32_t h0, l0, h1, l1;
            split2(v.x, v.y, h0, l0);
            split2(v.z, v.w, h1, l1);
            *(uint2*)&AsH[row * AS_STRIDE + cp] = make_uint2(h0, h1);
            *(uint2*)&AsL[row * AS_STRIDE + cp] = make_uint2(l0, l1);
        }
        __syncthreads();

#pragma unroll
        for (int kt = 0; kt < 4; kt++) {
            int ktg = ch * 4 + kt;
            uint32_t aH[2][4], aL[2][4];
#pragma unroll
            for (int m = 0; m < 2; m++) {
                int r0 = warpM * 32 + m * 16 + g;
                int r1 = r0 + 8;
                int cb = kt * 16 + 2 * t;
                aH[m][0] = *(const uint32_t*)&AsH[r0 * AS_STRIDE + cb];
                aH[m][1] = *(const uint32_t*)&AsH[r1 * AS_STRIDE + cb];
                aH[m][2] = *(const uint32_t*)&AsH[r0 * AS_STRIDE + cb + 8];
                aH[m][3] = *(const uint32_t*)&AsH[r1 * AS_STRIDE + cb + 8];
                aL[m][0] = *(const uint32_t*)&AsL[r0 * AS_STRIDE + cb];
                aL[m][1] = *(const uint32_t*)&AsL[r1 * AS_STRIDE + cb];
                aL[m][2] = *(const uint32_t*)&AsL[r0 * AS_STRIDE + cb + 8];
                aL[m][3] = *(const uint32_t*)&AsL[r1 * AS_STRIDE + cb + 8];
            }
            const uint2* bh = g_bfragH + ((size_t)(IMG * 8 + ktg) * 16 + warpN * 8) * 32 + lane;
            const uint2* bl = g_bfragL + ((size_t)(IMG * 8 + ktg) * 16 + warpN * 8) * 32 + lane;
#pragma unroll
            for (int nt = 0; nt < 8; nt++) {
                uint2 bH = bh[nt * 32];
                uint2 bL = bl[nt * 32];
#pragma unroll
                for (int m = 0; m < 2; m++) {
                    mma_bf16(c[m][nt], aH[m][0], aH[m][1], aH[m][2], aH[m][3], bH.x, bH.y);
                    mma_bf16(c[m][nt], aH[m][0], aH[m][1], aH[m][2], aH[m][3], bL.x, bL.y);
                    mma_bf16(c[m][nt], aL[m][0], aL[m][1], aL[m][2], aL[m][3], bH.x, bH.y);
                }
            }
        }
    }

    if (FINAL == 0) {
        // ---- standard epilogue: bias/relu + store C ----
#pragma unroll
        for (int m = 0; m < 2; m++) {
            int r0 = rowBase + warpM * 32 + m * 16 + g;
            int r1 = r0 + 8;
#pragma unroll
            for (int nt = 0; nt < 8; nt++) {
                int cn = warpN * 64 + nt * 8 + 2 * t;
                float v0 = c[m][nt][0], v1 = c[m][nt][1];
                float v2 = c[m][nt][2], v3 = c[m][nt][3];
                if (EPI >= 1) {
                    float b0 = sbias[cn], b1 = sbias[cn + 1];
                    v0 += b0; v1 += b1; v2 += b0; v3 += b1;
                }
                if (EPI == 2) {
                    v0 = fmaxf(v0, 0.0f); v1 = fmaxf(v1, 0.0f);
                    v2 = fmaxf(v2, 0.0f); v3 = fmaxf(v3, 0.0f);
                }
                *(float2*)(Cm + (size_t)r0 * D + cn) = make_float2(v0, v1);
                *(float2*)(Cm + (size_t)r1 * D + cn) = make_float2(v2, v3);
            }
        }
    } else {
        // ---- fused final: logits = relu(C+bias) @ W2, then log_softmax ----
        __syncthreads();                       // mainloop smem reads done
        float* sW2  = (float*)AsH;             // [128*8]
        float* slog = (float*)AsL;             // [128*16] (row, warpN*8+c)
#pragma unroll
        for (int i = 0; i < 4; i++) sW2[tid + i * 256] = w2[tid + i * 256];
#pragma unroll
        for (int i = 0; i < 8; i++) slog[tid * 8 + i] = 0.0f;
        __syncthreads();

        float lp[4][8];
#pragma unroll
        for (int ri = 0; ri < 4; ri++)
#pragma unroll
            for (int cc = 0; cc < 8; cc++) lp[ri][cc] = 0.0f;

#pragma unroll
        for (int m = 0; m < 2; m++) {
#pragma unroll
            for (int nt = 0; nt < 8; nt++) {
                int cn = warpN * 64 + nt * 8 + 2 * t;
                float v0 = c[m][nt][0] + sbias[cn];
                float v1 = c[m][nt][1] + sbias[cn + 1];
                float v2 = c[m][nt][2] + sbias[cn];
                float v3 = c[m][nt][3] + sbias[cn + 1];
                v0 = fmaxf(v0, 0.0f); v1 = fmaxf(v1, 0.0f);
                v2 = fmaxf(v2, 0.0f); v3 = fmaxf(v3, 0.0f);
                const float* w0 = sW2 + cn * 8;
                const float* w1 = sW2 + (cn + 1) * 8;
#pragma unroll
                for (int cc = 0; cc < 8; cc++) {
                    lp[m * 2 + 0][cc] = fmaf(v0, w0[cc], lp[m * 2 + 0][cc]);
                    lp[m * 2 + 0][cc] = fmaf(v1, w1[cc], lp[m * 2 + 0][cc]);
                    lp[m * 2 + 1][cc] = fmaf(v2, w0[cc], lp[m * 2 + 1][cc]);
                    lp[m * 2 + 1][cc] = fmaf(v3, w1[cc], lp[m * 2 + 1][cc]);
                }
            }
        }
        // reduce across the 4 t-lanes (lane bits 0..1)
#pragma unroll
        for (int off = 1; off <= 2; off <<= 1)
#pragma unroll
            for (int ri = 0; ri < 4; ri++)
#pragma unroll
                for (int cc = 0; cc < 8; cc++)
                    lp[ri][cc] += __shfl_xor_sync(0xffffffffu, lp[ri][cc], off);
        if (t == 0) {
#pragma unroll
            for (int ri = 0; ri < 4; ri++) {
                int m = ri >> 1, half = ri & 1;
                int row = warpM * 32 + m * 16 + half * 8 + g;
#pragma unroll
                for (int cc = 0; cc < 8; cc++)
                    slog[row * 16 + warpN * 8 + cc] = lp[ri][cc];
            }
        }
        __syncthreads();
        if (tid < 128) {
            float lg[8];
            float mx = -1e30f;
#pragma unroll
            for (int cc = 0; cc < 8; cc++) {
                lg[cc] = slog[tid * 16 + cc] + slog[tid * 16 + 8 + cc] + b2[cc];
                mx = fmaxf(mx, lg[cc]);
            }
            float se = 0.0f;
#pragma unroll
            for (int cc = 0; cc < 8; cc++) se += expf(lg[cc] - mx);
            float lse = logf(se) + mx;
            float4* o4 = (float4*)(pout + (size_t)(rowBase + tid) * C_OUT);
            o4[0] = make_float4(lg[0] - lse, lg[1] - lse, lg[2] - lse, lg[3] - lse);
            o4[1] = make_float4(lg[4] - lse, lg[5] - lse, lg[6] - lse, lg[7] - lse);
        }
    }
}

// ---------------- CSR gather: acc[d] = dinv_d^2 t[d] + dinv_d Σ dinv_s t[s] -
template<int TSEL, int OSEL>
__global__ __launch_bounds__(256) void gather_kernel() {
    const float* t = buf_ptr_dev(TSEL);
    float* acc = buf_ptr_dev(OSEL);
    int node = blockIdx.x * 8 + (threadIdx.x >> 5);
    int lane = threadIdx.x & 31;
    int p0 = g_ptr[node];
    int p1 = g_ptr[node + 1];
    float dd = g_dinv[node];
    float4 a = ((const float4*)(t + (size_t)node * D))[lane];
    float nn = dd * dd;
    a.x *= nn; a.y *= nn; a.z *= nn; a.w *= nn;
    for (int p = p0; p < p1; p++) {
        int s = g_csr_src[p];
        float ns = g_dinv[s] * dd;
        float4 v = ((const float4*)(t + (size_t)s * D))[lane];
        a.x = fmaf(v.x, ns, a.x);
        a.y = fmaf(v.y, ns, a.y);
        a.z = fmaf(v.z, ns, a.z);
        a.w = fmaf(v.w, ns, a.w);
    }
    ((float4*)(acc + (size_t)node * D))[lane] = a;
}

// ---------------- per-graph bias ----------------
__global__ void gbias_kernel(const int* __restrict__ sidx, const int* __restrict__ didx,
                             const float* __restrict__ ff_w, const float* __restrict__ ff_b,
                             const float* __restrict__ gcn2_b) {
    int b = blockIdx.x;
    int c = threadIdx.x;
    int srow = sidx[b] + b * N_PER;
    int drow = didx[b] + b * N_PER;
    const float* hs = g_bufC + (size_t)srow * D;
    const float* hd = g_bufC + (size_t)drow * D;
    float acc = ff_b[c];
    for (int k = 0; k < D; k++) {
        float b2 = gcn2_b[k];
        acc = fmaf(b2,         ff_w[k * D + c],           acc);
        acc = fmaf(hs[k] + b2, ff_w[(D + k) * D + c],     acc);
        acc = fmaf(hd[k] + b2, ff_w[(2 * D + k) * D + c], acc);
    }
    g_gbias[b * D + c] = acc;
}

// ---------------- batch-norm stats / finalize ----------------
template<int SEL>
__global__ void bn_stats_kernel() {
    const float* h = buf_ptr_dev(SEL);
    int col  = threadIdx.x & 127;
    int half = threadIdx.x >> 7;
    int rEnd = blockIdx.x * 256 + 256;
    float s = 0.0f, q = 0.0f;
    for (int r = blockIdx.x * 256 + half; r < rEnd; r += 2) {
        float v = h[(size_t)r * D + col];
        s += v;
        q = fmaf(v, v, q);
    }
    atomicAdd(&g_sum[col], s);
    atomicAdd(&g_sumsq[col], q);
}
__global__ void bn_fin_kernel(const float* __restrict__ gamma, const float* __restrict__ beta) {
    int c = threadIdx.x;
    float inv_n = 1.0f / (float)N_NODES;
    float mean = g_sum[c] * inv_n;
    float var  = g_sumsq[c] * inv_n - mean * mean;
    float rstd = rsqrtf(var + 1e-5f);
    float sc = gamma[c] * rstd;
    g_scale[c] = sc;
    g_shift[c] = beta[c] - mean * sc;
}

// ---------------- launch (kernel launches ONLY — graph-capture safe) -------
extern "C" void kernel_launch(void* const* d_in, const int* in_sizes, int n_in,
                              void* d_out, int out_size) {
    const float* x      = (const float*)d_in[0];
    const int*   ei     = (const int*)  d_in[1];
    const int*   sidx   = (const int*)  d_in[2];
    const int*   didx   = (const int*)  d_in[3];
    const float* emb_w  = (const float*)d_in[4];
    const float* emb_b  = (const float*)d_in[5];
    const float* gcn1_w = (const float*)d_in[6];
    const float* gcn1_b = (const float*)d_in[7];
    const float* gcn2_w = (const float*)d_in[8];
    const float* gcn2_b = (const float*)d_in[9];
    const float* bn_g   = (const float*)d_in[10];
    const float* bn_b   = (const float*)d_in[11];
    const float* ff_w   = (const float*)d_in[12];
    const float* ff_b   = (const float*)d_in[13];
    const float* ff1_w  = (const float*)d_in[14];
    const float* ff1_b  = (const float*)d_in[15];
    const float* ff2_w  = (const float*)d_in[16];
    const float* ff2_b  = (const float*)d_in[17];
    float* out = (float*)d_out;

    const int* src = ei;
    const int* dst = ei + E_EDGES;
    const int GM = N_NODES / 128;   // 512 gemm blocks

    // degree + CSR build (dinv fused into scan1) + weight prep
    deg_init_kernel<<<N_NODES / 256, 256>>>();
    deg_count_kernel<<<E_EDGES / 256, 256>>>(dst);
    scan1_kernel<<<256, 256>>>();
    scan2_kernel<<<1, 256>>>();
    scan3_kernel<<<256, 256>>>();
    fill_kernel<<<E_EDGES / 256, 256>>>(src, dst);
    prep_w_kernel<<<17, 128>>>(emb_w, emb_b, gcn1_w);
    prep_bfrag_kernel<<<64, 256>>>(gcn2_w, ff_w, ff1_w);

    // GCN1: t1 = x@(We W1) + (be W1) -> bufB ; gather -> bufC
    tcgemm<0,1,0,2,0,1,0><<<GM, 256>>>(x, nullptr, nullptr, nullptr, nullptr, nullptr);
    gather_kernel<2, 3><<<N_NODES / 8, 256>>>();

    // GCN2: A = relu(acc1 + b1) from bufC, t2 -> bufB ; gather -> bufC
    tcgemm<1,0,3,2,1,0,0><<<GM, 256>>>(nullptr, nullptr, gcn1_b, nullptr, nullptr, nullptr);
    gather_kernel<2, 3><<<N_NODES / 8, 256>>>();

    // per-graph bias (ff_b + b2@Wf + src/dest gathered terms)
    gbias_kernel<<<BATCH, D>>>(sidx, didx, ff_w, ff_b, gcn2_b);

    // ff: h3 = acc2 @ Wf[0:128] + gbias -> bufA
    tcgemm<0,3,3,1,2,0,0><<<GM, 256>>>(nullptr, nullptr, nullptr, nullptr, nullptr, nullptr);
    bn_stats_kernel<1><<<N_NODES / 256, 256>>>();
    bn_fin_kernel<<<1, D>>>(bn_g, bn_b);

    // ff1 + final fused: log_softmax(relu(bnrelu(h3)@W1f+b1f) @ W2 + b2) -> out
    tcgemm<2,2,1,2,3,0,1><<<GM, 256>>>(nullptr, ff1_b, nullptr, ff2_w, ff2_b, out);
}